// round 2
// baseline (speedup 1.0000x reference)
#include <cuda_runtime.h>
#include <cuda_bf16.h>

constexpr int cV = 32000, cH = 1024, cB = 32, cT = 64;
constexpr int cM = cB * cT;           // 2048
constexpr int cG = 3 * cH;            // 3072
constexpr long long cBTV = (long long)cB * cT * cV;

__device__ __align__(16) float         g_X[cM * cH];
__device__ __align__(16) float         g_gi[(size_t)cM * cG];
__device__ __align__(16) float         g_hs[cT * cB * cH];
__device__ __align__(16) __nv_bfloat16 g_hsb[cM * cH];         // [b*T+t][H]
__device__ __align__(16) __nv_bfloat16 g_wob[(size_t)cV * cH];
__device__ float g_lse[cM];

__device__ __forceinline__ unsigned f2tf(float f) {
    unsigned u; asm("cvt.rna.tf32.f32 %0, %1;" : "=r"(u) : "f"(f)); return u;
}
__device__ __forceinline__ void mma_tf32(float* c, const unsigned* a, unsigned b0, unsigned b1) {
    asm volatile("mma.sync.aligned.m16n8k8.row.col.f32.tf32.tf32.f32 "
        "{%0,%1,%2,%3}, {%4,%5,%6,%7}, {%8,%9}, {%0,%1,%2,%3};\n"
        : "+f"(c[0]), "+f"(c[1]), "+f"(c[2]), "+f"(c[3])
        : "r"(a[0]), "r"(a[1]), "r"(a[2]), "r"(a[3]), "r"(b0), "r"(b1));
}
__device__ __forceinline__ void mma_bf16(float* c, const unsigned* a, unsigned b0, unsigned b1) {
    asm volatile("mma.sync.aligned.m16n8k16.row.col.f32.bf16.bf16.f32 "
        "{%0,%1,%2,%3}, {%4,%5,%6,%7}, {%8,%9}, {%0,%1,%2,%3};\n"
        : "+f"(c[0]), "+f"(c[1]), "+f"(c[2]), "+f"(c[3])
        : "r"(a[0]), "r"(a[1]), "r"(a[2]), "r"(a[3]), "r"(b0), "r"(b1));
}

// ---- K1a: relu(embedding[token]) -> g_X, rows m = t*B + b --------------------
__global__ void k_embed(const int* __restrict__ target, const float* __restrict__ emb) {
    int m = blockIdx.x, t = m >> 5, b = m & 31;
    int tok = (t == 0) ? 1 : target[b * cT + (t - 1)];
    float4 v = ((const float4*)(emb + (size_t)tok * cH))[threadIdx.x];
    v.x = fmaxf(v.x, 0.f); v.y = fmaxf(v.y, 0.f); v.z = fmaxf(v.z, 0.f); v.w = fmaxf(v.w, 0.f);
    ((float4*)(g_X + (size_t)m * cH))[threadIdx.x] = v;
}

// ---- K1b: w_out -> bf16 ------------------------------------------------------
__global__ void k_cvt_wout(const float* __restrict__ w) {
    size_t i = (size_t)blockIdx.x * 1024 + threadIdx.x * 4;
    float4 v = *(const float4*)(w + i);
    *(__nv_bfloat162*)(g_wob + i)     = __floats2bfloat162_rn(v.x, v.y);
    *(__nv_bfloat162*)(g_wob + i + 2) = __floats2bfloat162_rn(v.z, v.w);
}

// ---- K2: gi = X @ w_ih^T + b_ih  (2048 x 3072 x 1024), tf32 ------------------
__global__ __launch_bounds__(128) void k_gi(const float* __restrict__ Wih,
                                            const float* __restrict__ bih) {
    constexpr int PAD = 20;
    __shared__ unsigned sA[2][64 * PAD], sB[2][64 * PAD];
    const int m0 = blockIdx.x * 64, n0 = blockIdx.y * 64;
    const int tid = threadIdx.x, lane = tid & 31;
    const int w = tid >> 5, wm = w & 1, wn = w >> 1;
    const int g = lane >> 2, q = lane & 3;
    float acc[2][4][4];
#pragma unroll
    for (int a = 0; a < 2; a++)
#pragma unroll
        for (int b = 0; b < 4; b++)
#pragma unroll
            for (int c = 0; c < 4; c++) acc[a][b][c] = 0.f;
    float4 ra[2], rb[2];
    auto loadG = [&](int kc) {
#pragma unroll
        for (int j = 0; j < 2; ++j) {
            int f = tid * 2 + j, row = f >> 2, c = (f & 3) * 4;
            ra[j] = *(const float4*)(g_X + (size_t)(m0 + row) * cH + kc + c);
            rb[j] = *(const float4*)(Wih + (size_t)(n0 + row) * cH + kc + c);
        }
    };
    auto storeS = [&](int buf) {
#pragma unroll
        for (int j = 0; j < 2; ++j) {
            int f = tid * 2 + j, row = f >> 2, c = (f & 3) * 4;
            unsigned* pa = &sA[buf][row * PAD + c];
            pa[0] = f2tf(ra[j].x); pa[1] = f2tf(ra[j].y); pa[2] = f2tf(ra[j].z); pa[3] = f2tf(ra[j].w);
            unsigned* pb = &sB[buf][row * PAD + c];
            pb[0] = f2tf(rb[j].x); pb[1] = f2tf(rb[j].y); pb[2] = f2tf(rb[j].z); pb[3] = f2tf(rb[j].w);
        }
    };
    loadG(0); storeS(0); __syncthreads();
    constexpr int NC = cH / 16;
    for (int ch = 0; ch < NC; ++ch) {
        int cur = ch & 1;
        if (ch + 1 < NC) loadG((ch + 1) * 16);
#pragma unroll
        for (int kt = 0; kt < 2; ++kt) {
            int kk = kt * 8;
            unsigned a[2][4];
#pragma unroll
            for (int mt = 0; mt < 2; ++mt) {
                int r = wm * 32 + mt * 16 + g;
                a[mt][0] = sA[cur][r * PAD + kk + q];
                a[mt][1] = sA[cur][(r + 8) * PAD + kk + q];
                a[mt][2] = sA[cur][r * PAD + kk + q + 4];
                a[mt][3] = sA[cur][(r + 8) * PAD + kk + q + 4];
            }
#pragma unroll
            for (int nt = 0; nt < 4; ++nt) {
                int c = wn * 32 + nt * 8 + g;
                unsigned b0 = sB[cur][c * PAD + kk + q];
                unsigned b1 = sB[cur][c * PAD + kk + q + 4];
                mma_tf32(acc[0][nt], a[0], b0, b1);
                mma_tf32(acc[1][nt], a[1], b0, b1);
            }
        }
        if (ch + 1 < NC) { storeS((ch + 1) & 1); __syncthreads(); }
    }
#pragma unroll
    for (int mt = 0; mt < 2; ++mt)
#pragma unroll
        for (int nt = 0; nt < 4; ++nt) {
            int row = m0 + wm * 32 + mt * 16 + g;
            int col = n0 + wn * 32 + nt * 8 + 2 * q;
            float b0 = bih[col], b1 = bih[col + 1];
            g_gi[(size_t)row * cG + col]           = acc[mt][nt][0] + b0;
            g_gi[(size_t)row * cG + col + 1]       = acc[mt][nt][1] + b1;
            g_gi[(size_t)(row + 8) * cG + col]     = acc[mt][nt][2] + b0;
            g_gi[(size_t)(row + 8) * cG + col + 1] = acc[mt][nt][3] + b1;
        }
}

// ---- K3: one GRU step; each CTA owns 16 hidden units (48 Whh rows) -----------
__global__ __launch_bounds__(128) void k_step(int t, const float* __restrict__ h0,
                                              const float* __restrict__ Whh,
                                              const float* __restrict__ bhh) {
    constexpr int PAD = 36;
    __shared__ unsigned sH[2][32 * PAD], sW[2][48 * PAD];
    __shared__ float sGH[32][49];
    const float* hprev = (t == 0) ? h0 : (g_hs + (size_t)(t - 1) * cB * cH);
    const int u0 = blockIdx.x * 16;
    const int tid = threadIdx.x, lane = tid & 31;
    const int w = tid >> 5, wm = w & 1, wn = w >> 1;
    const int g = lane >> 2, q = lane & 3;
    float acc[3][4];
#pragma unroll
    for (int a = 0; a < 3; a++)
#pragma unroll
        for (int c = 0; c < 4; c++) acc[a][c] = 0.f;
    float4 rh[2], rw[3];
    auto loadG = [&](int kc) {
#pragma unroll
        for (int j = 0; j < 2; ++j) {
            int f = tid * 2 + j, row = f >> 3, c = (f & 7) * 4;
            rh[j] = *(const float4*)(hprev + (size_t)row * cH + kc + c);
        }
#pragma unroll
        for (int j = 0; j < 3; ++j) {
            int f = tid * 3 + j, row = f >> 3, c = (f & 7) * 4;
            int grow = (row >> 4) * cH + u0 + (row & 15);
            rw[j] = *(const float4*)(Whh + (size_t)grow * cH + kc + c);
        }
    };
    auto storeS = [&](int buf) {
#pragma unroll
        for (int j = 0; j < 2; ++j) {
            int f = tid * 2 + j, row = f >> 3, c = (f & 7) * 4;
            unsigned* p = &sH[buf][row * PAD + c];
            p[0] = f2tf(rh[j].x); p[1] = f2tf(rh[j].y); p[2] = f2tf(rh[j].z); p[3] = f2tf(rh[j].w);
        }
#pragma unroll
        for (int j = 0; j < 3; ++j) {
            int f = tid * 3 + j, row = f >> 3, c = (f & 7) * 4;
            unsigned* p = &sW[buf][row * PAD + c];
            p[0] = f2tf(rw[j].x); p[1] = f2tf(rw[j].y); p[2] = f2tf(rw[j].z); p[3] = f2tf(rw[j].w);
        }
    };
    loadG(0); storeS(0); __syncthreads();
    constexpr int NC = cH / 32;
    for (int ch = 0; ch < NC; ++ch) {
        int cur = ch & 1;
        if (ch + 1 < NC) loadG((ch + 1) * 32);
#pragma unroll
        for (int kt = 0; kt < 4; ++kt) {
            int kk = kt * 8;
            unsigned a[4];
            int r = wm * 16 + g;
            a[0] = sH[cur][r * PAD + kk + q];
            a[1] = sH[cur][(r + 8) * PAD + kk + q];
            a[2] = sH[cur][r * PAD + kk + q + 4];
            a[3] = sH[cur][(r + 8) * PAD + kk + q + 4];
#pragma unroll
            for (int nt = 0; nt < 3; ++nt) {
                int c = wn * 24 + nt * 8 + g;
                unsigned b0 = sW[cur][c * PAD + kk + q];
                unsigned b1 = sW[cur][c * PAD + kk + q + 4];
                mma_tf32(acc[nt], a, b0, b1);
            }
        }
        if (ch + 1 < NC) { storeS((ch + 1) & 1); __syncthreads(); }
    }
#pragma unroll
    for (int nt = 0; nt < 3; ++nt) {
        int row = wm * 16 + g, col = wn * 24 + nt * 8 + 2 * q;
        sGH[row][col]         = acc[nt][0];
        sGH[row][col + 1]     = acc[nt][1];
        sGH[row + 8][col]     = acc[nt][2];
        sGH[row + 8][col + 1] = acc[nt][3];
    }
    __syncthreads();
    int b = tid & 31;
    const float* gi = g_gi + ((size_t)t * cB + b) * cG;
#pragma unroll
    for (int i = 0; i < 4; ++i) {
        int u = (tid >> 5) * 4 + i, ug = u0 + u;
        float pr = gi[ug]      + sGH[b][u]      + bhh[ug];
        float pz = gi[cH + ug] + sGH[b][16 + u] + bhh[cH + ug];
        float hn = sGH[b][32 + u] + bhh[2 * cH + ug];
        float r = 1.f / (1.f + expf(-pr));
        float z = 1.f / (1.f + expf(-pz));
        float n = tanhf(gi[2 * cH + ug] + r * hn);
        float ho = hprev[(size_t)b * cH + ug];
        float hv = (1.f - z) * n + z * ho;
        g_hs[((size_t)t * cB + b) * cH + ug] = hv;
        g_hsb[((size_t)b * cT + t) * cH + ug] = __float2bfloat16(hv);
    }
}

// ---- K4: logits = hs_bf16 @ w_out^T + b_out (2048 x 32000 x 1024) ------------
__global__ __launch_bounds__(256) void k_logits(const float* __restrict__ bout,
                                                float* __restrict__ out) {
    constexpr int PAD = 40;
    __shared__ __nv_bfloat16 sA[2][128 * PAD], sB[2][64 * PAD];
    const int m0 = blockIdx.x * 128, n0 = blockIdx.y * 64;
    const int tid = threadIdx.x, lane = tid & 31;
    const int w = tid >> 5, wm = w & 3, wn = w >> 2;
    const int g = lane >> 2, q = lane & 3;
    float acc[2][4][4];
#pragma unroll
    for (int a = 0; a < 2; a++)
#pragma unroll
        for (int b = 0; b < 4; b++)
#pragma unroll
            for (int c = 0; c < 4; c++) acc[a][b][c] = 0.f;
    uint4 ra[2], rb;
    auto loadG = [&](int kc) {
#pragma unroll
        for (int j = 0; j < 2; ++j) {
            int f = tid * 2 + j, row = f >> 2, c = (f & 3) * 8;
            ra[j] = *(const uint4*)(g_hsb + (size_t)(m0 + row) * cH + kc + c);
        }
        { int row = tid >> 2, c = (tid & 3) * 8;
          rb = *(const uint4*)(g_wob + (size_t)(n0 + row) * cH + kc + c); }
    };
    auto storeS = [&](int buf) {
#pragma unroll
        for (int j = 0; j < 2; ++j) {
            int f = tid * 2 + j, row = f >> 2, c = (f & 3) * 8;
            *(uint4*)&sA[buf][row * PAD + c] = ra[j];
        }
        { int row = tid >> 2, c = (tid & 3) * 8;
          *(uint4*)&sB[buf][row * PAD + c] = rb; }
    };
    loadG(0); storeS(0); __syncthreads();
    constexpr int NC = cH / 32;
    for (int ch = 0; ch < NC; ++ch) {
        int cur = ch & 1;
        if (ch + 1 < NC) loadG((ch + 1) * 32);
#pragma unroll
        for (int kt = 0; kt < 2; ++kt) {
            int kk = kt * 16;
            unsigned a[2][4];
#pragma unroll
            for (int mt = 0; mt < 2; ++mt) {
                int r = wm * 32 + mt * 16 + g;
                a[mt][0] = *(const unsigned*)&sA[cur][r * PAD + kk + 2 * q];
                a[mt][1] = *(const unsigned*)&sA[cur][(r + 8) * PAD + kk + 2 * q];
                a[mt][2] = *(const unsigned*)&sA[cur][r * PAD + kk + 2 * q + 8];
                a[mt][3] = *(const unsigned*)&sA[cur][(r + 8) * PAD + kk + 2 * q + 8];
            }
#pragma unroll
            for (int nt = 0; nt < 4; ++nt) {
                int c = wn * 32 + nt * 8 + g;
                unsigned b0 = *(const unsigned*)&sB[cur][c * PAD + kk + 2 * q];
                unsigned b1 = *(const unsigned*)&sB[cur][c * PAD + kk + 2 * q + 8];
                mma_bf16(acc[0][nt], a[0], b0, b1);
                mma_bf16(acc[1][nt], a[1], b0, b1);
            }
        }
        if (ch + 1 < NC) { storeS((ch + 1) & 1); __syncthreads(); }
    }
#pragma unroll
    for (int mt = 0; mt < 2; ++mt)
#pragma unroll
        for (int nt = 0; nt < 4; ++nt) {
            int row = m0 + wm * 32 + mt * 16 + g;
            int col = n0 + wn * 32 + nt * 8 + 2 * q;
            float b0 = bout[col], b1 = bout[col + 1];
            out[(size_t)row * cV + col]           = acc[mt][nt][0] + b0;
            out[(size_t)row * cV + col + 1]       = acc[mt][nt][1] + b1;
            out[(size_t)(row + 8) * cV + col]     = acc[mt][nt][2] + b0;
            out[(size_t)(row + 8) * cV + col + 1] = acc[mt][nt][3] + b1;
        }
}

// ---- K5: per-row log-sum-exp (logits bounded: no max pass needed) ------------
__global__ __launch_bounds__(256) void k_lse(const float* __restrict__ out) {
    __shared__ float red[256];
    int row = blockIdx.x;
    const float4* p = (const float4*)(out + (size_t)row * cV);
    float s = 0.f;
    for (int i = threadIdx.x; i < cV / 4; i += 256) {
        float4 v = p[i];
        s += expf(v.x) + expf(v.y) + expf(v.z) + expf(v.w);
    }
    red[threadIdx.x] = s; __syncthreads();
    for (int o = 128; o > 0; o >>= 1) {
        if (threadIdx.x < o) red[threadIdx.x] += red[threadIdx.x + o];
        __syncthreads();
    }
    if (threadIdx.x == 0) g_lse[row] = logf(red[0]);
}

// ---- K6: subtract lse in-place + write final hidden [1,B,H] ------------------
__global__ __launch_bounds__(256) void k_sub(float* __restrict__ out) {
    int bx = blockIdx.x;
    if (bx < cM) {
        float l = g_lse[bx];
        float4* p = (float4*)(out + (size_t)bx * cV);
        for (int i = threadIdx.x; i < cV / 4; i += 256) {
            float4 v = p[i];
            v.x -= l; v.y -= l; v.z -= l; v.w -= l;
            p[i] = v;
        }
    } else {
        int b = bx - cM;  // copy h_last
        const float4* src = (const float4*)(g_hs + ((size_t)(cT - 1) * cB + b) * cH);
        float4* dst = (float4*)(out + cBTV + (size_t)b * cH);
        dst[threadIdx.x] = src[threadIdx.x];
    }
}

extern "C" void kernel_launch(void* const* d_in, const int* in_sizes, int n_in,
                              void* d_out, int out_size) {
    const float* enc_hidden = (const float*)d_in[1];
    const int*   target     = (const int*)d_in[2];
    const float* emb        = (const float*)d_in[3];
    const float* w_ih       = (const float*)d_in[4];
    const float* w_hh       = (const float*)d_in[5];
    const float* b_ih       = (const float*)d_in[6];
    const float* b_hh       = (const float*)d_in[7];
    const float* w_out      = (const float*)d_in[8];
    const float* b_out      = (const float*)d_in[9];
    float* out = (float*)d_out;

    k_embed<<<cM, 256>>>(target, emb);
    k_cvt_wout<<<cV, 256>>>(w_out);
    k_gi<<<dim3(cM / 64, cG / 64), 128>>>(w_ih, b_ih);
    for (int t = 0; t < cT; ++t)
        k_step<<<64, 128>>>(t, enc_hidden, w_hh, b_hh);
    k_logits<<<dim3(cM / 128, cV / 64), 256>>>(b_out, out);
    k_lse<<<cM, 256>>>(out);
    k_sub<<<cM + cB, 256>>>(out);
}

// round 4
// speedup vs baseline: 1.3164x; 1.3164x over previous
#include <cuda_runtime.h>
#include <cuda_bf16.h>

constexpr int cV = 32000, cH = 1024, cB = 32, cT = 64;
constexpr int cM = cB * cT;           // 2048
constexpr int cG = 3 * cH;            // 3072
constexpr long long cBTV = (long long)cB * cT * cV;

constexpr int NCTA = 128;             // recurrence CTAs (1 per SM, all resident)
constexpr int UPC  = 8;               // hidden units per CTA
constexpr int RTHREADS = 96;          // 3 warps: one per gate (r,z,n)

__device__ __align__(16) float         g_X[cM * cH];
__device__ __align__(16) float         g_gi[(size_t)cM * cG];
__device__ __align__(16) unsigned      g_htf[2][cB * cH];      // tf32 h ping-pong
__device__ __align__(16) __nv_bfloat16 g_hsb[cM * cH];         // [b*T+t][H]
__device__ __align__(16) __nv_bfloat16 g_wob[(size_t)cV * cH];
__device__ float g_lse[cM];
__device__ unsigned g_bar;

__device__ __forceinline__ unsigned f2tf(float f) {
    unsigned u; asm("cvt.rna.tf32.f32 %0, %1;" : "=r"(u) : "f"(f)); return u;
}
__device__ __forceinline__ unsigned smem_u32(const void* p) {
    unsigned a;
    asm("{ .reg .u64 t; cvta.to.shared.u64 t, %1; cvt.u32.u64 %0, t; }" : "=r"(a) : "l"(p));
    return a;
}
__device__ __forceinline__ void mma_tf32(float* c, const unsigned* a, unsigned b0, unsigned b1) {
    asm volatile("mma.sync.aligned.m16n8k8.row.col.f32.tf32.tf32.f32 "
        "{%0,%1,%2,%3}, {%4,%5,%6,%7}, {%8,%9}, {%0,%1,%2,%3};\n"
        : "+f"(c[0]), "+f"(c[1]), "+f"(c[2]), "+f"(c[3])
        : "r"(a[0]), "r"(a[1]), "r"(a[2]), "r"(a[3]), "r"(b0), "r"(b1));
}
__device__ __forceinline__ void mma_bf16(float* c, const unsigned* a, unsigned b0, unsigned b1) {
    asm volatile("mma.sync.aligned.m16n8k16.row.col.f32.bf16.bf16.f32 "
        "{%0,%1,%2,%3}, {%4,%5,%6,%7}, {%8,%9}, {%0,%1,%2,%3};\n"
        : "+f"(c[0]), "+f"(c[1]), "+f"(c[2]), "+f"(c[3])
        : "r"(a[0]), "r"(a[1]), "r"(a[2]), "r"(a[3]), "r"(b0), "r"(b1));
}

// ---- K1a: relu(embedding[token]) -> g_X, rows m = t*B + b --------------------
__global__ void k_embed(const int* __restrict__ target, const float* __restrict__ emb) {
    int m = blockIdx.x, t = m >> 5, b = m & 31;
    int tok = (t == 0) ? 1 : target[b * cT + (t - 1)];
    float4 v = ((const float4*)(emb + (size_t)tok * cH))[threadIdx.x];
    v.x = fmaxf(v.x, 0.f); v.y = fmaxf(v.y, 0.f); v.z = fmaxf(v.z, 0.f); v.w = fmaxf(v.w, 0.f);
    ((float4*)(g_X + (size_t)m * cH))[threadIdx.x] = v;
}

// ---- K1b: w_out -> bf16 ------------------------------------------------------
__global__ void k_cvt_wout(const float* __restrict__ w) {
    size_t i = (size_t)blockIdx.x * 1024 + threadIdx.x * 4;
    float4 v = *(const float4*)(w + i);
    *(__nv_bfloat162*)(g_wob + i)     = __floats2bfloat162_rn(v.x, v.y);
    *(__nv_bfloat162*)(g_wob + i + 2) = __floats2bfloat162_rn(v.z, v.w);
}

// ---- K1c: h0 -> tf32 buffer 0, reset barrier ---------------------------------
__global__ void k_h0(const float* __restrict__ h0) {
    int i = blockIdx.x * 256 + threadIdx.x;     // grid 128 x 256 = 32768
    g_htf[0][i] = f2tf(h0[i]);
    if (i == 0) g_bar = 0;
}

// ---- K2: gi = X @ w_ih^T + b_ih  (2048 x 3072 x 1024), tf32 ------------------
__global__ __launch_bounds__(128) void k_gi(const float* __restrict__ Wih,
                                            const float* __restrict__ bih) {
    constexpr int PAD = 20;
    __shared__ unsigned sA[2][64 * PAD], sB[2][64 * PAD];
    const int m0 = blockIdx.x * 64, n0 = blockIdx.y * 64;
    const int tid = threadIdx.x, lane = tid & 31;
    const int w = tid >> 5, wm = w & 1, wn = w >> 1;
    const int g = lane >> 2, q = lane & 3;
    float acc[2][4][4];
#pragma unroll
    for (int a = 0; a < 2; a++)
#pragma unroll
        for (int b = 0; b < 4; b++)
#pragma unroll
            for (int c = 0; c < 4; c++) acc[a][b][c] = 0.f;
    float4 ra[2], rb[2];
    auto loadG = [&](int kc) {
#pragma unroll
        for (int j = 0; j < 2; ++j) {
            int f = tid * 2 + j, row = f >> 2, c = (f & 3) * 4;
            ra[j] = *(const float4*)(g_X + (size_t)(m0 + row) * cH + kc + c);
            rb[j] = *(const float4*)(Wih + (size_t)(n0 + row) * cH + kc + c);
        }
    };
    auto storeS = [&](int buf) {
#pragma unroll
        for (int j = 0; j < 2; ++j) {
            int f = tid * 2 + j, row = f >> 2, c = (f & 3) * 4;
            unsigned* pa = &sA[buf][row * PAD + c];
            pa[0] = f2tf(ra[j].x); pa[1] = f2tf(ra[j].y); pa[2] = f2tf(ra[j].z); pa[3] = f2tf(ra[j].w);
            unsigned* pb = &sB[buf][row * PAD + c];
            pb[0] = f2tf(rb[j].x); pb[1] = f2tf(rb[j].y); pb[2] = f2tf(rb[j].z); pb[3] = f2tf(rb[j].w);
        }
    };
    loadG(0); storeS(0); __syncthreads();
    constexpr int NC = cH / 16;
    for (int ch = 0; ch < NC; ++ch) {
        int cur = ch & 1;
        if (ch + 1 < NC) loadG((ch + 1) * 16);
#pragma unroll
        for (int kt = 0; kt < 2; ++kt) {
            int kk = kt * 8;
            unsigned a[2][4];
#pragma unroll
            for (int mt = 0; mt < 2; ++mt) {
                int r = wm * 32 + mt * 16 + g;
                a[mt][0] = sA[cur][r * PAD + kk + q];
                a[mt][1] = sA[cur][(r + 8) * PAD + kk + q];
                a[mt][2] = sA[cur][r * PAD + kk + q + 4];
                a[mt][3] = sA[cur][(r + 8) * PAD + kk + q + 4];
            }
#pragma unroll
            for (int nt = 0; nt < 4; ++nt) {
                int c = wn * 32 + nt * 8 + g;
                unsigned b0 = sB[cur][c * PAD + kk + q];
                unsigned b1 = sB[cur][c * PAD + kk + q + 4];
                mma_tf32(acc[0][nt], a[0], b0, b1);
                mma_tf32(acc[1][nt], a[1], b0, b1);
            }
        }
        if (ch + 1 < NC) { storeS((ch + 1) & 1); __syncthreads(); }
    }
#pragma unroll
    for (int mt = 0; mt < 2; ++mt)
#pragma unroll
        for (int nt = 0; nt < 4; ++nt) {
            int row = m0 + wm * 32 + mt * 16 + g;
            int col = n0 + wn * 32 + nt * 8 + 2 * q;
            float b0 = bih[col], b1 = bih[col + 1];
            g_gi[(size_t)row * cG + col]           = acc[mt][nt][0] + b0;
            g_gi[(size_t)row * cG + col + 1]       = acc[mt][nt][1] + b1;
            g_gi[(size_t)(row + 8) * cG + col]     = acc[mt][nt][2] + b0;
            g_gi[(size_t)(row + 8) * cG + col + 1] = acc[mt][nt][3] + b1;
        }
}

// ---- K3: persistent GRU recurrence ------------------------------------------
// 128 CTAs x 96 threads; CTA owns 8 units (24 w_hh rows resident in SMEM tf32).
// Warp w handles gate w (r/z/n): n-tile of 8 rows; M=32 batches = 2 m-tiles.
// Per step: stream h (tf32, L2) in 128-col chunks via cp.async.cg (L1 bypass),
// mma, fused gates, write h ping-pong + bf16 hs; global spin barrier.
constexpr int WSTR = 1028;   // 1024 + 4 pad words (conflict-free frag reads)
constexpr int HSTR = 132;    // 128 + 4 pad

__global__ __launch_bounds__(RTHREADS) void k_rnn(const float* __restrict__ h0,
                                                  const float* __restrict__ Whh,
                                                  const float* __restrict__ bhh,
                                                  float* __restrict__ outh) {
    extern __shared__ unsigned su[];
    unsigned* w_s  = su;                       // 24 * WSTR
    unsigned* h_s  = w_s + 24 * WSTR;          // 2 * 32 * HSTR
    float*    sGH  = (float*)(h_s + 2 * 32 * HSTR);  // 3 * 32 * 9
    float*    h_own = sGH + 3 * 32 * 9;        // 32 * 8
    float*    bhh_s = h_own + 32 * 8;          // 24

    const int tid = threadIdx.x, lane = tid & 31, w = tid >> 5;
    const int g = lane >> 2, q = lane & 3;
    const int u0 = blockIdx.x * UPC;

    // prologue: park this CTA's w_hh slice (rows gate*H + u0 + r) as tf32
    for (int i = tid; i < 24 * 256; i += RTHREADS) {      // float4 granularity
        int r = i >> 8, c4 = (i & 255) * 4;
        int gate = r >> 3, rr = r & 7;
        float4 v = *(const float4*)(Whh + ((size_t)gate * cH + u0 + rr) * cH + c4);
        unsigned* p = &w_s[r * WSTR + c4];
        p[0] = f2tf(v.x); p[1] = f2tf(v.y); p[2] = f2tf(v.z); p[3] = f2tf(v.w);
    }
    if (tid < 24) bhh_s[tid] = bhh[(tid >> 3) * cH + u0 + (tid & 7)];
    for (int i = tid; i < 32 * 8; i += RTHREADS)
        h_own[i] = h0[(i >> 3) * cH + u0 + (i & 7)];
    __syncthreads();

    for (int t = 0; t < cT; ++t) {
        const unsigned* hsrc = g_htf[t & 1];
        auto ldchunk = [&](int ki, int buf) {
            int kc = ki * 128;
            for (int i = tid; i < 1024; i += RTHREADS) {  // 1024 uint4 per chunk
                int r = i >> 5, c4 = (i & 31) * 4;
                unsigned dst = smem_u32(&h_s[buf * 32 * HSTR + r * HSTR + c4]);
                asm volatile("cp.async.cg.shared.global [%0], [%1], 16;\n"
                             :: "r"(dst), "l"(hsrc + r * cH + kc + c4));
            }
            asm volatile("cp.async.commit_group;\n");
        };
        ldchunk(0, 0);
        float acc[2][4] = {{0.f,0.f,0.f,0.f},{0.f,0.f,0.f,0.f}};
        for (int ki = 0; ki < 8; ++ki) {
            if (ki + 1 < 8) {
                ldchunk(ki + 1, (ki + 1) & 1);
                asm volatile("cp.async.wait_group 1;\n");
            } else {
                asm volatile("cp.async.wait_group 0;\n");
            }
            __syncthreads();
            const unsigned* hb = &h_s[(ki & 1) * 32 * HSTR];
            const unsigned* wb = &w_s[w * 8 * WSTR + ki * 128];
#pragma unroll
            for (int kk = 0; kk < 16; ++kk) {
                int kcol = kk * 8;
                unsigned b0 = wb[g * WSTR + kcol + q];
                unsigned b1 = wb[g * WSTR + kcol + q + 4];
#pragma unroll
                for (int mt = 0; mt < 2; ++mt) {
                    unsigned a[4];
                    a[0] = hb[(mt * 16 + g) * HSTR + kcol + q];
                    a[1] = hb[(mt * 16 + g + 8) * HSTR + kcol + q];
                    a[2] = hb[(mt * 16 + g) * HSTR + kcol + q + 4];
                    a[3] = hb[(mt * 16 + g + 8) * HSTR + kcol + q + 4];
                    mma_tf32(acc[mt], a, b0, b1);
                }
            }
            __syncthreads();
        }
        // deposit gh: sGH[gate][b][u] (u stride 9)
        float* sg = sGH + w * (32 * 9);
#pragma unroll
        for (int mt = 0; mt < 2; ++mt) {
            sg[(mt * 16 + g) * 9 + 2 * q]         = acc[mt][0];
            sg[(mt * 16 + g) * 9 + 2 * q + 1]     = acc[mt][1];
            sg[(mt * 16 + g + 8) * 9 + 2 * q]     = acc[mt][2];
            sg[(mt * 16 + g + 8) * 9 + 2 * q + 1] = acc[mt][3];
        }
        __syncthreads();
        // fused gates for our 32x8 outputs
        for (int i = tid; i < 256; i += RTHREADS) {
            int b = i >> 3, u = i & 7;
            const float* gi = g_gi + ((size_t)t * cB + b) * cG + u0 + u;
            float pr = gi[0]      + sGH[0 * 288 + b * 9 + u] + bhh_s[u];
            float pz = gi[cH]     + sGH[1 * 288 + b * 9 + u] + bhh_s[8 + u];
            float hn = sGH[2 * 288 + b * 9 + u] + bhh_s[16 + u];
            float r = 1.f / (1.f + expf(-pr));
            float z = 1.f / (1.f + expf(-pz));
            float n = tanhf(gi[2 * cH] + r * hn);
            float hv = (1.f - z) * n + z * h_own[i];
            h_own[i] = hv;
            g_htf[(t + 1) & 1][b * cH + u0 + u] = f2tf(hv);
            g_hsb[((size_t)b * cT + t) * cH + u0 + u] = __float2bfloat16(hv);
            if (t == cT - 1) outh[b * cH + u0 + u] = hv;
        }
        __threadfence();
        __syncthreads();
        if (tid == 0) {
            atomicAdd(&g_bar, 1u);
            unsigned target = (unsigned)NCTA * (t + 1);
            while (*(volatile unsigned*)&g_bar < target) { }
        }
        __syncthreads();
        __threadfence();
    }
}

// ---- K4: logits = hs_bf16 @ w_out^T + b_out (2048 x 32000 x 1024) ------------
__global__ __launch_bounds__(256) void k_logits(const float* __restrict__ bout,
                                                float* __restrict__ out) {
    constexpr int PAD = 40;
    __shared__ __nv_bfloat16 sA[2][128 * PAD], sB[2][64 * PAD];
    const int m0 = blockIdx.x * 128, n0 = blockIdx.y * 64;
    const int tid = threadIdx.x, lane = tid & 31;
    const int w = tid >> 5, wm = w & 3, wn = w >> 2;
    const int g = lane >> 2, q = lane & 3;
    float acc[2][4][4];
#pragma unroll
    for (int a = 0; a < 2; a++)
#pragma unroll
        for (int b = 0; b < 4; b++)
#pragma unroll
            for (int c = 0; c < 4; c++) acc[a][b][c] = 0.f;
    uint4 ra[2], rb;
    auto loadG = [&](int kc) {
#pragma unroll
        for (int j = 0; j < 2; ++j) {
            int f = tid * 2 + j, row = f >> 2, c = (f & 3) * 8;
            ra[j] = *(const uint4*)(g_hsb + (size_t)(m0 + row) * cH + kc + c);
        }
        { int row = tid >> 2, c = (tid & 3) * 8;
          rb = *(const uint4*)(g_wob + (size_t)(n0 + row) * cH + kc + c); }
    };
    auto storeS = [&](int buf) {
#pragma unroll
        for (int j = 0; j < 2; ++j) {
            int f = tid * 2 + j, row = f >> 2, c = (f & 3) * 8;
            *(uint4*)&sA[buf][row * PAD + c] = ra[j];
        }
        { int row = tid >> 2, c = (tid & 3) * 8;
          *(uint4*)&sB[buf][row * PAD + c] = rb; }
    };
    loadG(0); storeS(0); __syncthreads();
    constexpr int NC = cH / 32;
    for (int ch = 0; ch < NC; ++ch) {
        int cur = ch & 1;
        if (ch + 1 < NC) loadG((ch + 1) * 32);
#pragma unroll
        for (int kt = 0; kt < 2; ++kt) {
            int kk = kt * 16;
            unsigned a[2][4];
#pragma unroll
            for (int mt = 0; mt < 2; ++mt) {
                int r = wm * 32 + mt * 16 + g;
                a[mt][0] = *(const unsigned*)&sA[cur][r * PAD + kk + 2 * q];
                a[mt][1] = *(const unsigned*)&sA[cur][(r + 8) * PAD + kk + 2 * q];
                a[mt][2] = *(const unsigned*)&sA[cur][r * PAD + kk + 2 * q + 8];
                a[mt][3] = *(const unsigned*)&sA[cur][(r + 8) * PAD + kk + 2 * q + 8];
            }
#pragma unroll
            for (int nt = 0; nt < 4; ++nt) {
                int c = wn * 32 + nt * 8 + g;
                unsigned b0 = *(const unsigned*)&sB[cur][c * PAD + kk + 2 * q];
                unsigned b1 = *(const unsigned*)&sB[cur][c * PAD + kk + 2 * q + 8];
                mma_bf16(acc[0][nt], a[0], b0, b1);
                mma_bf16(acc[1][nt], a[1], b0, b1);
            }
        }
        if (ch + 1 < NC) { storeS((ch + 1) & 1); __syncthreads(); }
    }
#pragma unroll
    for (int mt = 0; mt < 2; ++mt)
#pragma unroll
        for (int nt = 0; nt < 4; ++nt) {
            int row = m0 + wm * 32 + mt * 16 + g;
            int col = n0 + wn * 32 + nt * 8 + 2 * q;
            float b0 = bout[col], b1 = bout[col + 1];
            out[(size_t)row * cV + col]           = acc[mt][nt][0] + b0;
            out[(size_t)row * cV + col + 1]       = acc[mt][nt][1] + b1;
            out[(size_t)(row + 8) * cV + col]     = acc[mt][nt][2] + b0;
            out[(size_t)(row + 8) * cV + col + 1] = acc[mt][nt][3] + b1;
        }
}

// ---- K5: per-row log-sum-exp (logits bounded: no max pass needed) ------------
__global__ __launch_bounds__(256) void k_lse(const float* __restrict__ out) {
    __shared__ float red[256];
    int row = blockIdx.x;
    const float4* p = (const float4*)(out + (size_t)row * cV);
    float s = 0.f;
    for (int i = threadIdx.x; i < cV / 4; i += 256) {
        float4 v = p[i];
        s += expf(v.x) + expf(v.y) + expf(v.z) + expf(v.w);
    }
    red[threadIdx.x] = s; __syncthreads();
    for (int o = 128; o > 0; o >>= 1) {
        if (threadIdx.x < o) red[threadIdx.x] += red[threadIdx.x + o];
        __syncthreads();
    }
    if (threadIdx.x == 0) g_lse[row] = logf(red[0]);
}

// ---- K6: subtract lse in-place ----------------------------------------------
__global__ __launch_bounds__(256) void k_sub(float* __restrict__ out) {
    int row = blockIdx.x;
    float l = g_lse[row];
    float4* p = (float4*)(out + (size_t)row * cV);
    for (int i = threadIdx.x; i < cV / 4; i += 256) {
        float4 v = p[i];
        v.x -= l; v.y -= l; v.z -= l; v.w -= l;
        p[i] = v;
    }
}

extern "C" void kernel_launch(void* const* d_in, const int* in_sizes, int n_in,
                              void* d_out, int out_size) {
    const float* enc_hidden = (const float*)d_in[1];
    const int*   target     = (const int*)d_in[2];
    const float* emb        = (const float*)d_in[3];
    const float* w_ih       = (const float*)d_in[4];
    const float* w_hh       = (const float*)d_in[5];
    const float* b_ih       = (const float*)d_in[6];
    const float* b_hh       = (const float*)d_in[7];
    const float* w_out      = (const float*)d_in[8];
    const float* b_out      = (const float*)d_in[9];
    float* out = (float*)d_out;

    // dynamic smem for persistent recurrence kernel
    constexpr int RSMEM = (24 * WSTR + 2 * 32 * HSTR) * 4 + (3 * 32 * 9 + 32 * 8 + 24) * 4;
    cudaFuncSetAttribute(k_rnn, cudaFuncAttributeMaxDynamicSharedMemorySize, RSMEM);

    k_embed<<<cM, 256>>>(target, emb);
    k_cvt_wout<<<cV, 256>>>(w_out);
    k_h0<<<cB * cH / 256, 256>>>(enc_hidden);
    k_gi<<<dim3(cM / 64, cG / 64), 128>>>(w_ih, b_ih);
    k_rnn<<<NCTA, RTHREADS, RSMEM>>>(enc_hidden, w_hh, b_hh, out + cBTV);
    k_logits<<<dim3(cM / 128, cV / 64), 256>>>(b_out, out);
    k_lse<<<cM, 256>>>(out);
    k_sub<<<cM, 256>>>(out);
}

// round 7
// speedup vs baseline: 1.6081x; 1.2216x over previous
#include <cuda_runtime.h>
#include <cuda_bf16.h>
#include <cstdint>

constexpr int cV = 32000, cH = 1024, cB = 32, cT = 64;
constexpr int cM = cB * cT;           // 2048
constexpr int cG = 3 * cH;            // 3072
constexpr long long cBTV = (long long)cB * cT * cV;

constexpr int NCTA = 128;             // recurrence CTAs
constexpr int UPC  = 8;               // hidden units per CTA
constexpr int RTHREADS = 96;

__device__ __align__(16) unsigned      g_X[cM * cH];             // tf32 relu(embed)
__device__ __align__(16) unsigned      g_wihtf[(size_t)cG * cH]; // tf32 w_ih
__device__ __align__(16) float         g_gi[(size_t)cM * cG];
__device__ __align__(16) unsigned      g_htf[2][cB * cH];        // tf32 h ping-pong
__device__ __align__(16) __nv_bfloat16 g_hsb[cM * cH];           // [b*T+t][H]
__device__ __align__(16) __nv_bfloat16 g_wob[(size_t)cV * cH];
__device__ float g_sum[cM];
__device__ unsigned g_flags[NCTA * 32];   // 128B-strided barrier slots

__device__ __forceinline__ unsigned f2tf(float f) {
    unsigned u; asm("cvt.rna.tf32.f32 %0, %1;" : "=r"(u) : "f"(f)); return u;
}
__device__ __forceinline__ unsigned smem_u32(const void* p) {
    unsigned a;
    asm("{ .reg .u64 t; cvta.to.shared.u64 t, %1; cvt.u32.u64 %0, t; }" : "=r"(a) : "l"(p));
    return a;
}
__device__ __forceinline__ void mma_tf32(float* c, const unsigned* a, unsigned b0, unsigned b1) {
    asm volatile("mma.sync.aligned.m16n8k8.row.col.f32.tf32.tf32.f32 "
        "{%0,%1,%2,%3}, {%4,%5,%6,%7}, {%8,%9}, {%0,%1,%2,%3};\n"
        : "+f"(c[0]), "+f"(c[1]), "+f"(c[2]), "+f"(c[3])
        : "r"(a[0]), "r"(a[1]), "r"(a[2]), "r"(a[3]), "r"(b0), "r"(b1));
}
__device__ __forceinline__ void mma_bf16(float* c, const unsigned* a, unsigned b0, unsigned b1) {
    asm volatile("mma.sync.aligned.m16n8k16.row.col.f32.bf16.bf16.f32 "
        "{%0,%1,%2,%3}, {%4,%5,%6,%7}, {%8,%9}, {%0,%1,%2,%3};\n"
        : "+f"(c[0]), "+f"(c[1]), "+f"(c[2]), "+f"(c[3])
        : "r"(a[0]), "r"(a[1]), "r"(a[2]), "r"(a[3]), "r"(b0), "r"(b1));
}
__device__ __forceinline__ void cpasync16(unsigned dst, const void* src) {
    asm volatile("cp.async.cg.shared.global [%0], [%1], 16;\n" :: "r"(dst), "l"(src));
}

// ---- K1a: relu(embedding[token]) -> g_X (tf32) -------------------------------
__global__ void k_embed(const int* __restrict__ target, const float* __restrict__ emb) {
    int m = blockIdx.x, t = m >> 5, b = m & 31;
    int tok = (t == 0) ? 1 : target[b * cT + (t - 1)];
    float4 v = ((const float4*)(emb + (size_t)tok * cH))[threadIdx.x];
    uint4 o;
    o.x = f2tf(fmaxf(v.x, 0.f)); o.y = f2tf(fmaxf(v.y, 0.f));
    o.z = f2tf(fmaxf(v.z, 0.f)); o.w = f2tf(fmaxf(v.w, 0.f));
    ((uint4*)(g_X + (size_t)m * cH))[threadIdx.x] = o;
}

// ---- K1b: w_out -> bf16 ------------------------------------------------------
__global__ void k_cvt_wout(const float* __restrict__ w) {
    size_t i = (size_t)blockIdx.x * 1024 + threadIdx.x * 4;
    float4 v = *(const float4*)(w + i);
    *(__nv_bfloat162*)(g_wob + i)     = __floats2bfloat162_rn(v.x, v.y);
    *(__nv_bfloat162*)(g_wob + i + 2) = __floats2bfloat162_rn(v.z, v.w);
}

// ---- K1d: w_ih -> tf32 -------------------------------------------------------
__global__ void k_cvt_wih(const float* __restrict__ w) {
    size_t i = (size_t)blockIdx.x * 1024 + threadIdx.x * 4;
    float4 v = *(const float4*)(w + i);
    uint4 o; o.x = f2tf(v.x); o.y = f2tf(v.y); o.z = f2tf(v.z); o.w = f2tf(v.w);
    *(uint4*)(g_wihtf + i) = o;
}

// ---- K1c: h0 -> tf32 buffer 0, reset barrier flags + sums --------------------
__global__ void k_h0(const float* __restrict__ h0) {
    int i = blockIdx.x * 256 + threadIdx.x;
    g_htf[0][i] = f2tf(h0[i]);
    if (i < cM) g_sum[i] = 0.f;
    if (i < NCTA * 32) g_flags[i] = 0;
}

// ---- K2: gi = X @ w_ih^T + b_ih (tf32, operands pre-converted) ---------------
__global__ __launch_bounds__(128) void k_gi(const float* __restrict__ bih) {
    constexpr int PAD = 20;
    __shared__ unsigned sA[2][64 * PAD], sB[2][64 * PAD];
    const int m0 = blockIdx.x * 64, n0 = blockIdx.y * 64;
    const int tid = threadIdx.x, lane = tid & 31;
    const int w = tid >> 5, wm = w & 1, wn = w >> 1;
    const int g = lane >> 2, q = lane & 3;
    float acc[2][4][4];
#pragma unroll
    for (int a = 0; a < 2; a++)
#pragma unroll
        for (int b = 0; b < 4; b++)
#pragma unroll
            for (int c = 0; c < 4; c++) acc[a][b][c] = 0.f;
    uint4 ra[2], rb[2];
    auto loadG = [&](int kc) {
#pragma unroll
        for (int j = 0; j < 2; ++j) {
            int f = tid * 2 + j, row = f >> 2, c = (f & 3) * 4;
            ra[j] = *(const uint4*)(g_X + (size_t)(m0 + row) * cH + kc + c);
            rb[j] = *(const uint4*)(g_wihtf + (size_t)(n0 + row) * cH + kc + c);
        }
    };
    auto storeS = [&](int buf) {
#pragma unroll
        for (int j = 0; j < 2; ++j) {
            int f = tid * 2 + j, row = f >> 2, c = (f & 3) * 4;
            *(uint4*)&sA[buf][row * PAD + c] = ra[j];
            *(uint4*)&sB[buf][row * PAD + c] = rb[j];
        }
    };
    loadG(0); storeS(0); __syncthreads();
    constexpr int NC = cH / 16;
    for (int ch = 0; ch < NC; ++ch) {
        int cur = ch & 1;
        if (ch + 1 < NC) loadG((ch + 1) * 16);
#pragma unroll
        for (int kt = 0; kt < 2; ++kt) {
            int kk = kt * 8;
            unsigned a[2][4];
#pragma unroll
            for (int mt = 0; mt < 2; ++mt) {
                int r = wm * 32 + mt * 16 + g;
                a[mt][0] = sA[cur][r * PAD + kk + q];
                a[mt][1] = sA[cur][(r + 8) * PAD + kk + q];
                a[mt][2] = sA[cur][r * PAD + kk + q + 4];
                a[mt][3] = sA[cur][(r + 8) * PAD + kk + q + 4];
            }
#pragma unroll
            for (int nt = 0; nt < 4; ++nt) {
                int c = wn * 32 + nt * 8 + g;
                unsigned b0 = sB[cur][c * PAD + kk + q];
                unsigned b1 = sB[cur][c * PAD + kk + q + 4];
                mma_tf32(acc[0][nt], a[0], b0, b1);
                mma_tf32(acc[1][nt], a[1], b0, b1);
            }
        }
        if (ch + 1 < NC) { storeS((ch + 1) & 1); __syncthreads(); }
    }
#pragma unroll
    for (int mt = 0; mt < 2; ++mt)
#pragma unroll
        for (int nt = 0; nt < 4; ++nt) {
            int row = m0 + wm * 32 + mt * 16 + g;
            int col = n0 + wn * 32 + nt * 8 + 2 * q;
            float b0 = bih[col], b1 = bih[col + 1];
            g_gi[(size_t)row * cG + col]           = acc[mt][nt][0] + b0;
            g_gi[(size_t)row * cG + col + 1]       = acc[mt][nt][1] + b1;
            g_gi[(size_t)(row + 8) * cG + col]     = acc[mt][nt][2] + b0;
            g_gi[(size_t)(row + 8) * cG + col + 1] = acc[mt][nt][3] + b1;
        }
}

// ---- K3: persistent GRU recurrence (tf32) ------------------------------------
constexpr int WSTR = 1028;
constexpr int HSTR = 132;

__global__ __launch_bounds__(RTHREADS) void k_rnn(const float* __restrict__ h0,
                                                  const float* __restrict__ Whh,
                                                  const float* __restrict__ bhh,
                                                  float* __restrict__ outh) {
    extern __shared__ unsigned su[];
    unsigned* w_s  = su;                        // 24 * WSTR
    unsigned* h_s  = w_s + 24 * WSTR;           // 2 * 32 * HSTR
    float*    sGH  = (float*)(h_s + 2 * 32 * HSTR);
    float*    h_own = sGH + 3 * 32 * 9;
    float*    bhh_s = h_own + 32 * 8;

    const int tid = threadIdx.x, lane = tid & 31, w = tid >> 5;
    const int g = lane >> 2, q = lane & 3;
    const int u0 = blockIdx.x * UPC;

    for (int i = tid; i < 24 * 256; i += RTHREADS) {
        int r = i >> 8, c4 = (i & 255) * 4;
        int gate = r >> 3, rr = r & 7;
        float4 v = *(const float4*)(Whh + ((size_t)gate * cH + u0 + rr) * cH + c4);
        unsigned* p = &w_s[r * WSTR + c4];
        p[0] = f2tf(v.x); p[1] = f2tf(v.y); p[2] = f2tf(v.z); p[3] = f2tf(v.w);
    }
    if (tid < 24) bhh_s[tid] = bhh[(tid >> 3) * cH + u0 + (tid & 7)];
    for (int i = tid; i < 32 * 8; i += RTHREADS)
        h_own[i] = h0[(i >> 3) * cH + u0 + (i & 7)];
    __syncthreads();

    for (int t = 0; t < cT; ++t) {
        float gr[3], gz[3], gn[3];
#pragma unroll
        for (int j = 0; j < 3; ++j) {
            int idx = tid + 96 * j;
            if (idx < 256) {
                int b = idx >> 3, u = idx & 7;
                const float* gi = g_gi + ((size_t)t * cB + b) * cG + u0 + u;
                gr[j] = gi[0]; gz[j] = gi[cH]; gn[j] = gi[2 * cH];
            }
        }
        const unsigned* hsrc = g_htf[t & 1];
        auto ldchunk = [&](int ki, int buf) {
            int kc = ki * 128;
            for (int i = tid; i < 1024; i += RTHREADS) {
                int r = i >> 5, c4 = (i & 31) * 4;
                cpasync16(smem_u32(&h_s[buf * 32 * HSTR + r * HSTR + c4]), hsrc + r * cH + kc + c4);
            }
            asm volatile("cp.async.commit_group;\n");
        };
        ldchunk(0, 0);
        float acc[2][4] = {{0.f,0.f,0.f,0.f},{0.f,0.f,0.f,0.f}};
        for (int ki = 0; ki < 8; ++ki) {
            if (ki + 1 < 8) { ldchunk(ki + 1, (ki + 1) & 1); asm volatile("cp.async.wait_group 1;\n"); }
            else           { asm volatile("cp.async.wait_group 0;\n"); }
            __syncthreads();
            const unsigned* hb = &h_s[(ki & 1) * 32 * HSTR];
            const unsigned* wb = &w_s[w * 8 * WSTR + ki * 128];
#pragma unroll
            for (int kk = 0; kk < 16; ++kk) {
                int kcol = kk * 8;
                unsigned b0 = wb[g * WSTR + kcol + q];
                unsigned b1 = wb[g * WSTR + kcol + q + 4];
#pragma unroll
                for (int mt = 0; mt < 2; ++mt) {
                    unsigned a[4];
                    a[0] = hb[(mt * 16 + g) * HSTR + kcol + q];
                    a[1] = hb[(mt * 16 + g + 8) * HSTR + kcol + q];
                    a[2] = hb[(mt * 16 + g) * HSTR + kcol + q + 4];
                    a[3] = hb[(mt * 16 + g + 8) * HSTR + kcol + q + 4];
                    mma_tf32(acc[mt], a, b0, b1);
                }
            }
            __syncthreads();
        }
        float* sg = sGH + w * (32 * 9);
#pragma unroll
        for (int mt = 0; mt < 2; ++mt) {
            sg[(mt * 16 + g) * 9 + 2 * q]         = acc[mt][0];
            sg[(mt * 16 + g) * 9 + 2 * q + 1]     = acc[mt][1];
            sg[(mt * 16 + g + 8) * 9 + 2 * q]     = acc[mt][2];
            sg[(mt * 16 + g + 8) * 9 + 2 * q + 1] = acc[mt][3];
        }
        __syncthreads();
#pragma unroll
        for (int j = 0; j < 3; ++j) {
            int idx = tid + 96 * j;
            if (idx < 256) {
                int b = idx >> 3, u = idx & 7;
                float pr = gr[j] + sGH[0 * 288 + b * 9 + u] + bhh_s[u];
                float pz = gz[j] + sGH[1 * 288 + b * 9 + u] + bhh_s[8 + u];
                float hn = sGH[2 * 288 + b * 9 + u] + bhh_s[16 + u];
                float r = 1.f / (1.f + expf(-pr));
                float z = 1.f / (1.f + expf(-pz));
                float n = tanhf(gn[j] + r * hn);
                float hv = (1.f - z) * n + z * h_own[idx];
                h_own[idx] = hv;
                g_htf[(t + 1) & 1][b * cH + u0 + u] = f2tf(hv);
                g_hsb[((size_t)b * cT + t) * cH + u0 + u] = __float2bfloat16(hv);
                if (t == cT - 1) outh[b * cH + u0 + u] = hv;
            }
        }
        __threadfence();
        __syncthreads();
        if (tid == 0) ((volatile unsigned*)g_flags)[blockIdx.x * 32] = t + 1;
        {
            int s0 = tid;
            while (((volatile unsigned*)g_flags)[s0 * 32] < (unsigned)(t + 1)) { }
            if (tid < NCTA - 96) {
                int s1 = tid + 96;
                while (((volatile unsigned*)g_flags)[s1 * 32] < (unsigned)(t + 1)) { }
            }
        }
        __syncthreads();
        __threadfence();
    }
}

// ---- K4: logits = hs_bf16 @ w_out^T + b_out (bf16 HMMA, 128x128 tile) --------
// Fused epilogue: bias add, store, per-row exp partial sums -> g_sum atomics.
__global__ __launch_bounds__(256) void k_logits(const float* __restrict__ bout,
                                                float* __restrict__ out) {
    constexpr int PAD = 40;
    __shared__ __nv_bfloat16 sA[2][128 * PAD], sB[2][128 * PAD];
    __shared__ float srow[128];
    __shared__ float sbias[128];
    const int m0 = blockIdx.x * 128, n0 = blockIdx.y * 128;
    const int tid = threadIdx.x, lane = tid & 31;
    const int w = tid >> 5, wm = w & 1, wn = w >> 1;   // 2 (m) x 4 (n) warps
    const int g = lane >> 2, q = lane & 3;

    if (tid < 128) { srow[tid] = 0.f; sbias[tid] = bout[n0 + tid]; }

    float acc[4][4][4];
#pragma unroll
    for (int a = 0; a < 4; a++)
#pragma unroll
        for (int b = 0; b < 4; b++)
#pragma unroll
            for (int c = 0; c < 4; c++) acc[a][b][c] = 0.f;

    uint4 ra[2], rb[2];
    auto loadG = [&](int kc) {
#pragma unroll
        for (int j = 0; j < 2; ++j) {
            int f = tid * 2 + j, row = f >> 2, c = (f & 3) * 8;
            ra[j] = *(const uint4*)(g_hsb + (size_t)(m0 + row) * cH + kc + c);
            rb[j] = *(const uint4*)(g_wob + (size_t)(n0 + row) * cH + kc + c);
        }
    };
    auto storeS = [&](int buf) {
#pragma unroll
        for (int j = 0; j < 2; ++j) {
            int f = tid * 2 + j, row = f >> 2, c = (f & 3) * 8;
            *(uint4*)&sA[buf][row * PAD + c] = ra[j];
            *(uint4*)&sB[buf][row * PAD + c] = rb[j];
        }
    };
    loadG(0); storeS(0); __syncthreads();
    constexpr int NC = cH / 32;
    for (int ch = 0; ch < NC; ++ch) {
        int cur = ch & 1;
        if (ch + 1 < NC) loadG((ch + 1) * 32);
#pragma unroll
        for (int kt = 0; kt < 2; ++kt) {
            int kk = kt * 16;
            unsigned a[4][4];
#pragma unroll
            for (int mt = 0; mt < 4; ++mt) {
                int r = wm * 64 + mt * 16 + g;
                a[mt][0] = *(const unsigned*)&sA[cur][r * PAD + kk + 2 * q];
                a[mt][1] = *(const unsigned*)&sA[cur][(r + 8) * PAD + kk + 2 * q];
                a[mt][2] = *(const unsigned*)&sA[cur][r * PAD + kk + 2 * q + 8];
                a[mt][3] = *(const unsigned*)&sA[cur][(r + 8) * PAD + kk + 2 * q + 8];
            }
#pragma unroll
            for (int nt = 0; nt < 4; ++nt) {
                int c = wn * 32 + nt * 8 + g;
                unsigned b0 = *(const unsigned*)&sB[cur][c * PAD + kk + 2 * q];
                unsigned b1 = *(const unsigned*)&sB[cur][c * PAD + kk + 2 * q + 8];
#pragma unroll
                for (int mt = 0; mt < 4; ++mt)
                    mma_bf16(acc[mt][nt], a[mt], b0, b1);
            }
        }
        if (ch + 1 < NC) { storeS((ch + 1) & 1); __syncthreads(); }
    }

    // epilogue: bias + store + exp partial sums
    float es[4][2];
#pragma unroll
    for (int mt = 0; mt < 4; ++mt) { es[mt][0] = 0.f; es[mt][1] = 0.f; }
#pragma unroll
    for (int mt = 0; mt < 4; ++mt)
#pragma unroll
        for (int nt = 0; nt < 4; ++nt) {
            int row = m0 + wm * 64 + mt * 16 + g;
            int lc  = wn * 32 + nt * 8 + 2 * q;
            int col = n0 + lc;
            float v0 = acc[mt][nt][0] + sbias[lc];
            float v1 = acc[mt][nt][1] + sbias[lc + 1];
            float v2 = acc[mt][nt][2] + sbias[lc];
            float v3 = acc[mt][nt][3] + sbias[lc + 1];
            out[(size_t)row * cV + col]           = v0;
            out[(size_t)row * cV + col + 1]       = v1;
            out[(size_t)(row + 8) * cV + col]     = v2;
            out[(size_t)(row + 8) * cV + col + 1] = v3;
            es[mt][0] += __expf(v0) + __expf(v1);
            es[mt][1] += __expf(v2) + __expf(v3);
        }
    // reduce over the q-quad (lanes g*4+q share rows)
#pragma unroll
    for (int mt = 0; mt < 4; ++mt)
#pragma unroll
        for (int h = 0; h < 2; ++h) {
            es[mt][h] += __shfl_xor_sync(0xFFFFFFFFu, es[mt][h], 1);
            es[mt][h] += __shfl_xor_sync(0xFFFFFFFFu, es[mt][h], 2);
        }
    if (q == 0) {
#pragma unroll
        for (int mt = 0; mt < 4; ++mt) {
            atomicAdd(&srow[wm * 64 + mt * 16 + g], es[mt][0]);
            atomicAdd(&srow[wm * 64 + mt * 16 + g + 8], es[mt][1]);
        }
    }
    __syncthreads();
    if (tid < 128) atomicAdd(&g_sum[m0 + tid], srow[tid]);
}

// ---- K6: subtract log(sum) in-place ------------------------------------------
__global__ __launch_bounds__(256) void k_sub(float* __restrict__ out) {
    int row = blockIdx.x;
    float l = logf(g_sum[row]);
    float4* p = (float4*)(out + (size_t)row * cV);
    for (int i = threadIdx.x; i < cV / 4; i += 256) {
        float4 v = p[i];
        v.x -= l; v.y -= l; v.z -= l; v.w -= l;
        p[i] = v;
    }
}

extern "C" void kernel_launch(void* const* d_in, const int* in_sizes, int n_in,
                              void* d_out, int out_size) {
    const float* enc_hidden = (const float*)d_in[1];
    const int*   target     = (const int*)d_in[2];
    const float* emb        = (const float*)d_in[3];
    const float* w_ih       = (const float*)d_in[4];
    const float* w_hh       = (const float*)d_in[5];
    const float* b_ih       = (const float*)d_in[6];
    const float* b_hh       = (const float*)d_in[7];
    const float* w_out      = (const float*)d_in[8];
    const float* b_out      = (const float*)d_in[9];
    float* out = (float*)d_out;

    constexpr int RSMEM = (24 * WSTR + 2 * 32 * HSTR) * 4 + (3 * 32 * 9 + 32 * 8 + 24) * 4;
    cudaFuncSetAttribute(k_rnn, cudaFuncAttributeMaxDynamicSharedMemorySize, RSMEM);

    k_embed<<<cM, 256>>>(target, emb);
    k_cvt_wout<<<cV, 256>>>(w_out);
    k_cvt_wih<<<cG, 256>>>(w_ih);
    k_h0<<<cB * cH / 256, 256>>>(enc_hidden);
    k_gi<<<dim3(cM / 64, cG / 64), 128>>>(b_ih);
    k_rnn<<<NCTA, RTHREADS, RSMEM>>>(enc_hidden, w_hh, b_hh, out + cBTV);
    k_logits<<<dim3(cM / 128, cV / 128), 256>>>(b_out, out);
    k_sub<<<cM, 256>>>(out);
}

// round 8
// speedup vs baseline: 1.7089x; 1.0627x over previous
#include <cuda_runtime.h>
#include <cuda_bf16.h>
#include <cstdint>

constexpr int cV = 32000, cH = 1024, cB = 32, cT = 64;
constexpr int cM = cB * cT;           // 2048
constexpr int cG = 3 * cH;            // 3072
constexpr long long cBTV = (long long)cB * cT * cV;

constexpr int NCTA = 128;             // recurrence CTAs
constexpr int UPC  = 8;               // hidden units per CTA
constexpr int RTHREADS = 96;

__device__ __align__(16) unsigned      g_X[cM * cH];             // tf32 relu(embed)
__device__ __align__(16) unsigned      g_wihtf[(size_t)cG * cH]; // tf32 w_ih
__device__ __align__(16) float         g_gi[(size_t)cM * cG];
__device__ __align__(16) unsigned      g_htf[2][cB * cH];        // tf32 h ping-pong
__device__ __align__(16) __nv_bfloat16 g_hsb[cM * cH];           // [b*T+t][H]
__device__ __align__(16) __nv_bfloat16 g_wob[(size_t)cV * cH];
__device__ float g_sum[cM];
__device__ unsigned g_flags[NCTA * 32];   // 128B-strided barrier slots

__device__ __forceinline__ unsigned f2tf(float f) {
    unsigned u; asm("cvt.rna.tf32.f32 %0, %1;" : "=r"(u) : "f"(f)); return u;
}
__device__ __forceinline__ unsigned smem_u32(const void* p) {
    unsigned a;
    asm("{ .reg .u64 t; cvta.to.shared.u64 t, %1; cvt.u32.u64 %0, t; }" : "=r"(a) : "l"(p));
    return a;
}
__device__ __forceinline__ void mma_tf32(float* c, const unsigned* a, unsigned b0, unsigned b1) {
    asm volatile("mma.sync.aligned.m16n8k8.row.col.f32.tf32.tf32.f32 "
        "{%0,%1,%2,%3}, {%4,%5,%6,%7}, {%8,%9}, {%0,%1,%2,%3};\n"
        : "+f"(c[0]), "+f"(c[1]), "+f"(c[2]), "+f"(c[3])
        : "r"(a[0]), "r"(a[1]), "r"(a[2]), "r"(a[3]), "r"(b0), "r"(b1));
}
__device__ __forceinline__ void mma_bf16(float* c, const unsigned* a, unsigned b0, unsigned b1) {
    asm volatile("mma.sync.aligned.m16n8k16.row.col.f32.bf16.bf16.f32 "
        "{%0,%1,%2,%3}, {%4,%5,%6,%7}, {%8,%9}, {%0,%1,%2,%3};\n"
        : "+f"(c[0]), "+f"(c[1]), "+f"(c[2]), "+f"(c[3])
        : "r"(a[0]), "r"(a[1]), "r"(a[2]), "r"(a[3]), "r"(b0), "r"(b1));
}
__device__ __forceinline__ void ldmat4(unsigned* r, unsigned addr) {
    asm volatile("ldmatrix.sync.aligned.m8n8.x4.shared.b16 {%0,%1,%2,%3}, [%4];"
        : "=r"(r[0]), "=r"(r[1]), "=r"(r[2]), "=r"(r[3]) : "r"(addr));
}
__device__ __forceinline__ void cpasync16(unsigned dst, const void* src) {
    asm volatile("cp.async.cg.shared.global [%0], [%1], 16;\n" :: "r"(dst), "l"(src));
}

// ---- K1a: relu(embedding[token]) -> g_X (tf32) -------------------------------
__global__ void k_embed(const int* __restrict__ target, const float* __restrict__ emb) {
    int m = blockIdx.x, t = m >> 5, b = m & 31;
    int tok = (t == 0) ? 1 : target[b * cT + (t - 1)];
    float4 v = ((const float4*)(emb + (size_t)tok * cH))[threadIdx.x];
    uint4 o;
    o.x = f2tf(fmaxf(v.x, 0.f)); o.y = f2tf(fmaxf(v.y, 0.f));
    o.z = f2tf(fmaxf(v.z, 0.f)); o.w = f2tf(fmaxf(v.w, 0.f));
    ((uint4*)(g_X + (size_t)m * cH))[threadIdx.x] = o;
}

// ---- K1b: w_out -> bf16 ------------------------------------------------------
__global__ void k_cvt_wout(const float* __restrict__ w) {
    size_t i = (size_t)blockIdx.x * 1024 + threadIdx.x * 4;
    float4 v = *(const float4*)(w + i);
    *(__nv_bfloat162*)(g_wob + i)     = __floats2bfloat162_rn(v.x, v.y);
    *(__nv_bfloat162*)(g_wob + i + 2) = __floats2bfloat162_rn(v.z, v.w);
}

// ---- K1d: w_ih -> tf32 -------------------------------------------------------
__global__ void k_cvt_wih(const float* __restrict__ w) {
    size_t i = (size_t)blockIdx.x * 1024 + threadIdx.x * 4;
    float4 v = *(const float4*)(w + i);
    uint4 o; o.x = f2tf(v.x); o.y = f2tf(v.y); o.z = f2tf(v.z); o.w = f2tf(v.w);
    *(uint4*)(g_wihtf + i) = o;
}

// ---- K1c: h0 -> tf32 buffer 0, reset barrier flags + sums --------------------
__global__ void k_h0(const float* __restrict__ h0) {
    int i = blockIdx.x * 256 + threadIdx.x;
    g_htf[0][i] = f2tf(h0[i]);
    if (i < cM) g_sum[i] = 0.f;
    if (i < NCTA * 32) g_flags[i] = 0;
}

// ---- K2: gi = X @ w_ih^T + b_ih (tf32, operands pre-converted) ---------------
__global__ __launch_bounds__(128) void k_gi(const float* __restrict__ bih) {
    constexpr int PAD = 20;
    __shared__ unsigned sA[2][64 * PAD], sB[2][64 * PAD];
    const int m0 = blockIdx.x * 64, n0 = blockIdx.y * 64;
    const int tid = threadIdx.x, lane = tid & 31;
    const int w = tid >> 5, wm = w & 1, wn = w >> 1;
    const int g = lane >> 2, q = lane & 3;
    float acc[2][4][4];
#pragma unroll
    for (int a = 0; a < 2; a++)
#pragma unroll
        for (int b = 0; b < 4; b++)
#pragma unroll
            for (int c = 0; c < 4; c++) acc[a][b][c] = 0.f;
    uint4 ra[2], rb[2];
    auto loadG = [&](int kc) {
#pragma unroll
        for (int j = 0; j < 2; ++j) {
            int f = tid * 2 + j, row = f >> 2, c = (f & 3) * 4;
            ra[j] = *(const uint4*)(g_X + (size_t)(m0 + row) * cH + kc + c);
            rb[j] = *(const uint4*)(g_wihtf + (size_t)(n0 + row) * cH + kc + c);
        }
    };
    auto storeS = [&](int buf) {
#pragma unroll
        for (int j = 0; j < 2; ++j) {
            int f = tid * 2 + j, row = f >> 2, c = (f & 3) * 4;
            *(uint4*)&sA[buf][row * PAD + c] = ra[j];
            *(uint4*)&sB[buf][row * PAD + c] = rb[j];
        }
    };
    loadG(0); storeS(0); __syncthreads();
    constexpr int NC = cH / 16;
    for (int ch = 0; ch < NC; ++ch) {
        int cur = ch & 1;
        if (ch + 1 < NC) loadG((ch + 1) * 16);
#pragma unroll
        for (int kt = 0; kt < 2; ++kt) {
            int kk = kt * 8;
            unsigned a[2][4];
#pragma unroll
            for (int mt = 0; mt < 2; ++mt) {
                int r = wm * 32 + mt * 16 + g;
                a[mt][0] = sA[cur][r * PAD + kk + q];
                a[mt][1] = sA[cur][(r + 8) * PAD + kk + q];
                a[mt][2] = sA[cur][r * PAD + kk + q + 4];
                a[mt][3] = sA[cur][(r + 8) * PAD + kk + q + 4];
            }
#pragma unroll
            for (int nt = 0; nt < 4; ++nt) {
                int c = wn * 32 + nt * 8 + g;
                unsigned b0 = sB[cur][c * PAD + kk + q];
                unsigned b1 = sB[cur][c * PAD + kk + q + 4];
                mma_tf32(acc[0][nt], a[0], b0, b1);
                mma_tf32(acc[1][nt], a[1], b0, b1);
            }
        }
        if (ch + 1 < NC) { storeS((ch + 1) & 1); __syncthreads(); }
    }
#pragma unroll
    for (int mt = 0; mt < 2; ++mt)
#pragma unroll
        for (int nt = 0; nt < 4; ++nt) {
            int row = m0 + wm * 32 + mt * 16 + g;
            int col = n0 + wn * 32 + nt * 8 + 2 * q;
            float b0 = bih[col], b1 = bih[col + 1];
            g_gi[(size_t)row * cG + col]           = acc[mt][nt][0] + b0;
            g_gi[(size_t)row * cG + col + 1]       = acc[mt][nt][1] + b1;
            g_gi[(size_t)(row + 8) * cG + col]     = acc[mt][nt][2] + b0;
            g_gi[(size_t)(row + 8) * cG + col + 1] = acc[mt][nt][3] + b1;
        }
}

// ---- K3: persistent GRU recurrence (tf32) ------------------------------------
constexpr int WSTR = 1028;
constexpr int HSTR = 132;

__global__ __launch_bounds__(RTHREADS) void k_rnn(const float* __restrict__ h0,
                                                  const float* __restrict__ Whh,
                                                  const float* __restrict__ bhh,
                                                  float* __restrict__ outh) {
    extern __shared__ unsigned su[];
    unsigned* w_s  = su;                        // 24 * WSTR
    unsigned* h_s  = w_s + 24 * WSTR;           // 2 * 32 * HSTR
    float*    sGH  = (float*)(h_s + 2 * 32 * HSTR);
    float*    h_own = sGH + 3 * 32 * 9;
    float*    bhh_s = h_own + 32 * 8;

    const int tid = threadIdx.x, lane = tid & 31, w = tid >> 5;
    const int g = lane >> 2, q = lane & 3;
    const int u0 = blockIdx.x * UPC;

    for (int i = tid; i < 24 * 256; i += RTHREADS) {
        int r = i >> 8, c4 = (i & 255) * 4;
        int gate = r >> 3, rr = r & 7;
        float4 v = *(const float4*)(Whh + ((size_t)gate * cH + u0 + rr) * cH + c4);
        unsigned* p = &w_s[r * WSTR + c4];
        p[0] = f2tf(v.x); p[1] = f2tf(v.y); p[2] = f2tf(v.z); p[3] = f2tf(v.w);
    }
    if (tid < 24) bhh_s[tid] = bhh[(tid >> 3) * cH + u0 + (tid & 7)];
    for (int i = tid; i < 32 * 8; i += RTHREADS)
        h_own[i] = h0[(i >> 3) * cH + u0 + (i & 7)];
    __syncthreads();

    for (int t = 0; t < cT; ++t) {
        float gr[3], gz[3], gn[3];
#pragma unroll
        for (int j = 0; j < 3; ++j) {
            int idx = tid + 96 * j;
            if (idx < 256) {
                int b = idx >> 3, u = idx & 7;
                const float* gi = g_gi + ((size_t)t * cB + b) * cG + u0 + u;
                gr[j] = gi[0]; gz[j] = gi[cH]; gn[j] = gi[2 * cH];
            }
        }
        const unsigned* hsrc = g_htf[t & 1];
        auto ldchunk = [&](int ki, int buf) {
            int kc = ki * 128;
            for (int i = tid; i < 1024; i += RTHREADS) {
                int r = i >> 5, c4 = (i & 31) * 4;
                cpasync16(smem_u32(&h_s[buf * 32 * HSTR + r * HSTR + c4]), hsrc + r * cH + kc + c4);
            }
            asm volatile("cp.async.commit_group;\n");
        };
        ldchunk(0, 0);
        float acc[2][4] = {{0.f,0.f,0.f,0.f},{0.f,0.f,0.f,0.f}};
        for (int ki = 0; ki < 8; ++ki) {
            if (ki + 1 < 8) { ldchunk(ki + 1, (ki + 1) & 1); asm volatile("cp.async.wait_group 1;\n"); }
            else           { asm volatile("cp.async.wait_group 0;\n"); }
            __syncthreads();
            const unsigned* hb = &h_s[(ki & 1) * 32 * HSTR];
            const unsigned* wb = &w_s[w * 8 * WSTR + ki * 128];
#pragma unroll
            for (int kk = 0; kk < 16; ++kk) {
                int kcol = kk * 8;
                unsigned b0 = wb[g * WSTR + kcol + q];
                unsigned b1 = wb[g * WSTR + kcol + q + 4];
#pragma unroll
                for (int mt = 0; mt < 2; ++mt) {
                    unsigned a[4];
                    a[0] = hb[(mt * 16 + g) * HSTR + kcol + q];
                    a[1] = hb[(mt * 16 + g + 8) * HSTR + kcol + q];
                    a[2] = hb[(mt * 16 + g) * HSTR + kcol + q + 4];
                    a[3] = hb[(mt * 16 + g + 8) * HSTR + kcol + q + 4];
                    mma_tf32(acc[mt], a, b0, b1);
                }
            }
            __syncthreads();
        }
        float* sg = sGH + w * (32 * 9);
#pragma unroll
        for (int mt = 0; mt < 2; ++mt) {
            sg[(mt * 16 + g) * 9 + 2 * q]         = acc[mt][0];
            sg[(mt * 16 + g) * 9 + 2 * q + 1]     = acc[mt][1];
            sg[(mt * 16 + g + 8) * 9 + 2 * q]     = acc[mt][2];
            sg[(mt * 16 + g + 8) * 9 + 2 * q + 1] = acc[mt][3];
        }
        __syncthreads();
#pragma unroll
        for (int j = 0; j < 3; ++j) {
            int idx = tid + 96 * j;
            if (idx < 256) {
                int b = idx >> 3, u = idx & 7;
                float pr = gr[j] + sGH[0 * 288 + b * 9 + u] + bhh_s[u];
                float pz = gz[j] + sGH[1 * 288 + b * 9 + u] + bhh_s[8 + u];
                float hn = sGH[2 * 288 + b * 9 + u] + bhh_s[16 + u];
                float r = 1.f / (1.f + expf(-pr));
                float z = 1.f / (1.f + expf(-pz));
                float n = tanhf(gn[j] + r * hn);
                float hv = (1.f - z) * n + z * h_own[idx];
                h_own[idx] = hv;
                g_htf[(t + 1) & 1][b * cH + u0 + u] = f2tf(hv);
                g_hsb[((size_t)b * cT + t) * cH + u0 + u] = __float2bfloat16(hv);
                if (t == cT - 1) outh[b * cH + u0 + u] = hv;
            }
        }
        __threadfence();
        __syncthreads();
        if (tid == 0) ((volatile unsigned*)g_flags)[blockIdx.x * 32] = t + 1;
        {
            int s0 = tid;
            while (((volatile unsigned*)g_flags)[s0 * 32] < (unsigned)(t + 1)) { }
            if (tid < NCTA - 96) {
                int s1 = tid + 96;
                while (((volatile unsigned*)g_flags)[s1 * 32] < (unsigned)(t + 1)) { }
            }
        }
        __syncthreads();
        __threadfence();
    }
}

// ---- K4: logits GEMM (bf16 HMMA, 128x128 tile, ldmatrix frags) ---------------
__global__ __launch_bounds__(256) void k_logits(const float* __restrict__ bout,
                                                float* __restrict__ out) {
    constexpr int PAD = 40;
    __shared__ __nv_bfloat16 sA[2][128 * PAD], sB[2][128 * PAD];
    __shared__ float srow[128];
    __shared__ float sbias[128];
    const int m0 = blockIdx.x * 128, n0 = blockIdx.y * 128;
    const int tid = threadIdx.x, lane = tid & 31;
    const int w = tid >> 5, wm = w & 1, wn = w >> 1;   // 2 (m) x 4 (n) warps
    const int g = lane >> 2, q = lane & 3;
    // ldmatrix lane-derived offsets
    const int lr = lane & 7, lh = (lane >> 3) & 1, lq = lane >> 4;
    const int arow = lr + lh * 8, acol = lq * 8;        // A: mats (rowblk, kblk)
    const int brow = lr + lq * 8, bcol = lh * 8;        // B: mats (kblk, nblk)

    if (tid < 128) { srow[tid] = 0.f; sbias[tid] = bout[n0 + tid]; }

    float acc[4][4][4];
#pragma unroll
    for (int a = 0; a < 4; a++)
#pragma unroll
        for (int b = 0; b < 4; b++)
#pragma unroll
            for (int c = 0; c < 4; c++) acc[a][b][c] = 0.f;

    unsigned aBase[2] = { smem_u32(&sA[0][0]), smem_u32(&sA[1][0]) };
    unsigned bBase[2] = { smem_u32(&sB[0][0]), smem_u32(&sB[1][0]) };

    uint4 ra[2], rb[2];
    auto loadG = [&](int kc) {
#pragma unroll
        for (int j = 0; j < 2; ++j) {
            int f = tid * 2 + j, row = f >> 2, c = (f & 3) * 8;
            ra[j] = *(const uint4*)(g_hsb + (size_t)(m0 + row) * cH + kc + c);
            rb[j] = *(const uint4*)(g_wob + (size_t)(n0 + row) * cH + kc + c);
        }
    };
    auto storeS = [&](int buf) {
#pragma unroll
        for (int j = 0; j < 2; ++j) {
            int f = tid * 2 + j, row = f >> 2, c = (f & 3) * 8;
            *(uint4*)&sA[buf][row * PAD + c] = ra[j];
            *(uint4*)&sB[buf][row * PAD + c] = rb[j];
        }
    };
    loadG(0); storeS(0); __syncthreads();
    constexpr int NC = cH / 32;
    for (int ch = 0; ch < NC; ++ch) {
        int cur = ch & 1;
        if (ch + 1 < NC) loadG((ch + 1) * 32);
#pragma unroll
        for (int kt = 0; kt < 2; ++kt) {
            int kk = kt * 16;
            unsigned a[4][4], bf[2][4];
#pragma unroll
            for (int mt = 0; mt < 4; ++mt)
                ldmat4(a[mt], aBase[cur] +
                       (((wm * 64 + mt * 16 + arow) * PAD + kk + acol) << 1));
#pragma unroll
            for (int p = 0; p < 2; ++p)
                ldmat4(bf[p], bBase[cur] +
                       (((wn * 32 + p * 16 + brow) * PAD + kk + bcol) << 1));
#pragma unroll
            for (int nt = 0; nt < 4; ++nt) {
                unsigned b0 = bf[nt >> 1][(nt & 1) * 2];
                unsigned b1 = bf[nt >> 1][(nt & 1) * 2 + 1];
#pragma unroll
                for (int mt = 0; mt < 4; ++mt)
                    mma_bf16(acc[mt][nt], a[mt], b0, b1);
            }
        }
        if (ch + 1 < NC) { storeS((ch + 1) & 1); __syncthreads(); }
    }

    // epilogue: bias + store + exp partial sums
    float es[4][2];
#pragma unroll
    for (int mt = 0; mt < 4; ++mt) { es[mt][0] = 0.f; es[mt][1] = 0.f; }
#pragma unroll
    for (int mt = 0; mt < 4; ++mt)
#pragma unroll
        for (int nt = 0; nt < 4; ++nt) {
            int row = m0 + wm * 64 + mt * 16 + g;
            int lc  = wn * 32 + nt * 8 + 2 * q;
            int col = n0 + lc;
            float v0 = acc[mt][nt][0] + sbias[lc];
            float v1 = acc[mt][nt][1] + sbias[lc + 1];
            float v2 = acc[mt][nt][2] + sbias[lc];
            float v3 = acc[mt][nt][3] + sbias[lc + 1];
            out[(size_t)row * cV + col]           = v0;
            out[(size_t)row * cV + col + 1]       = v1;
            out[(size_t)(row + 8) * cV + col]     = v2;
            out[(size_t)(row + 8) * cV + col + 1] = v3;
            es[mt][0] += __expf(v0) + __expf(v1);
            es[mt][1] += __expf(v2) + __expf(v3);
        }
#pragma unroll
    for (int mt = 0; mt < 4; ++mt)
#pragma unroll
        for (int h = 0; h < 2; ++h) {
            es[mt][h] += __shfl_xor_sync(0xFFFFFFFFu, es[mt][h], 1);
            es[mt][h] += __shfl_xor_sync(0xFFFFFFFFu, es[mt][h], 2);
        }
    if (q == 0) {
#pragma unroll
        for (int mt = 0; mt < 4; ++mt) {
            atomicAdd(&srow[wm * 64 + mt * 16 + g], es[mt][0]);
            atomicAdd(&srow[wm * 64 + mt * 16 + g + 8], es[mt][1]);
        }
    }
    __syncthreads();
    if (tid < 128) atomicAdd(&g_sum[m0 + tid], srow[tid]);
}

// ---- K6: subtract log(sum) in-place (4 CTAs per row for concurrency) ---------
__global__ __launch_bounds__(256) void k_sub(float* __restrict__ out) {
    int row = blockIdx.x;
    float l = logf(g_sum[row]);
    const int seg = blockIdx.y;              // 0..3, 8000 elems each
    float4* p = (float4*)(out + (size_t)row * cV + seg * 8000);
    for (int i = threadIdx.x; i < 2000; i += 256) {
        float4 v = p[i];
        v.x -= l; v.y -= l; v.z -= l; v.w -= l;
        p[i] = v;
    }
}

extern "C" void kernel_launch(void* const* d_in, const int* in_sizes, int n_in,
                              void* d_out, int out_size) {
    const float* enc_hidden = (const float*)d_in[1];
    const int*   target     = (const int*)d_in[2];
    const float* emb        = (const float*)d_in[3];
    const float* w_ih       = (const float*)d_in[4];
    const float* w_hh       = (const float*)d_in[5];
    const float* b_ih       = (const float*)d_in[6];
    const float* b_hh       = (const float*)d_in[7];
    const float* w_out      = (const float*)d_in[8];
    const float* b_out      = (const float*)d_in[9];
    float* out = (float*)d_out;

    constexpr int RSMEM = (24 * WSTR + 2 * 32 * HSTR) * 4 + (3 * 32 * 9 + 32 * 8 + 24) * 4;
    cudaFuncSetAttribute(k_rnn, cudaFuncAttributeMaxDynamicSharedMemorySize, RSMEM);

    k_embed<<<cM, 256>>>(target, emb);
    k_cvt_wout<<<cV, 256>>>(w_out);
    k_cvt_wih<<<cG, 256>>>(w_ih);
    k_h0<<<cB * cH / 256, 256>>>(enc_hidden);
    k_gi<<<dim3(cM / 64, cG / 64), 128>>>(b_ih);
    k_rnn<<<NCTA, RTHREADS, RSMEM>>>(enc_hidden, w_hh, b_hh, out + cBTV);
    k_logits<<<dim3(cM / 128, cV / 128), 256>>>(b_out, out);
    k_sub<<<dim3(cM, 4), 256>>>(out);
}

// round 9
// speedup vs baseline: 1.9890x; 1.1639x over previous
#include <cuda_runtime.h>
#include <cuda_bf16.h>
#include <cstdint>

constexpr int cV = 32000, cH = 1024, cB = 32, cT = 64;
constexpr int cM = cB * cT;           // 2048
constexpr int cG = 3 * cH;            // 3072
constexpr long long cBTV = (long long)cB * cT * cV;

constexpr int NCTA = 128;             // recurrence CTAs
constexpr int UPC  = 8;               // hidden units per CTA
constexpr int RTHREADS = 96;

__device__ __align__(16) unsigned      g_X[cM * cH];             // tf32 relu(embed)
__device__ __align__(16) unsigned      g_wihtf[(size_t)cG * cH]; // tf32 w_ih
__device__ __align__(16) float         g_gi[(size_t)cM * cG];
__device__ __align__(16) unsigned      g_htf[2][cB * cH];        // tf32 h ping-pong
__device__ __align__(16) __nv_bfloat16 g_hsb[cM * cH];           // [b*T+t][H]
__device__ __align__(16) __nv_bfloat16 g_wob[(size_t)cV * cH];
__device__ float g_sum[cM];
__device__ unsigned g_flags[NCTA * 32];   // 128B-strided barrier slots

__device__ __forceinline__ unsigned f2tf(float f) {
    unsigned u; asm("cvt.rna.tf32.f32 %0, %1;" : "=r"(u) : "f"(f)); return u;
}
__device__ __forceinline__ unsigned smem_u32(const void* p) {
    unsigned a;
    asm("{ .reg .u64 t; cvta.to.shared.u64 t, %1; cvt.u32.u64 %0, t; }" : "=r"(a) : "l"(p));
    return a;
}
__device__ __forceinline__ void mma_tf32(float* c, const unsigned* a, unsigned b0, unsigned b1) {
    asm volatile("mma.sync.aligned.m16n8k8.row.col.f32.tf32.tf32.f32 "
        "{%0,%1,%2,%3}, {%4,%5,%6,%7}, {%8,%9}, {%0,%1,%2,%3};\n"
        : "+f"(c[0]), "+f"(c[1]), "+f"(c[2]), "+f"(c[3])
        : "r"(a[0]), "r"(a[1]), "r"(a[2]), "r"(a[3]), "r"(b0), "r"(b1));
}
__device__ __forceinline__ void mma_bf16(float* c, const unsigned* a, unsigned b0, unsigned b1) {
    asm volatile("mma.sync.aligned.m16n8k16.row.col.f32.bf16.bf16.f32 "
        "{%0,%1,%2,%3}, {%4,%5,%6,%7}, {%8,%9}, {%0,%1,%2,%3};\n"
        : "+f"(c[0]), "+f"(c[1]), "+f"(c[2]), "+f"(c[3])
        : "r"(a[0]), "r"(a[1]), "r"(a[2]), "r"(a[3]), "r"(b0), "r"(b1));
}
__device__ __forceinline__ void ldmat4(unsigned* r, unsigned addr) {
    asm volatile("ldmatrix.sync.aligned.m8n8.x4.shared.b16 {%0,%1,%2,%3}, [%4];"
        : "=r"(r[0]), "=r"(r[1]), "=r"(r[2]), "=r"(r[3]) : "r"(addr));
}
__device__ __forceinline__ void cpasync16(unsigned dst, const void* src) {
    asm volatile("cp.async.cg.shared.global [%0], [%1], 16;\n" :: "r"(dst), "l"(src));
}

// ---- K1a: relu(embedding[token]) -> g_X (tf32) -------------------------------
__global__ void k_embed(const int* __restrict__ target, const float* __restrict__ emb) {
    int m = blockIdx.x, t = m >> 5, b = m & 31;
    int tok = (t == 0) ? 1 : target[b * cT + (t - 1)];
    float4 v = ((const float4*)(emb + (size_t)tok * cH))[threadIdx.x];
    uint4 o;
    o.x = f2tf(fmaxf(v.x, 0.f)); o.y = f2tf(fmaxf(v.y, 0.f));
    o.z = f2tf(fmaxf(v.z, 0.f)); o.w = f2tf(fmaxf(v.w, 0.f));
    ((uint4*)(g_X + (size_t)m * cH))[threadIdx.x] = o;
}

// ---- K1b: w_out -> bf16 ------------------------------------------------------
__global__ void k_cvt_wout(const float* __restrict__ w) {
    size_t i = (size_t)blockIdx.x * 1024 + threadIdx.x * 4;
    float4 v = *(const float4*)(w + i);
    *(__nv_bfloat162*)(g_wob + i)     = __floats2bfloat162_rn(v.x, v.y);
    *(__nv_bfloat162*)(g_wob + i + 2) = __floats2bfloat162_rn(v.z, v.w);
}

// ---- K1d: w_ih -> tf32 -------------------------------------------------------
__global__ void k_cvt_wih(const float* __restrict__ w) {
    size_t i = (size_t)blockIdx.x * 1024 + threadIdx.x * 4;
    float4 v = *(const float4*)(w + i);
    uint4 o; o.x = f2tf(v.x); o.y = f2tf(v.y); o.z = f2tf(v.z); o.w = f2tf(v.w);
    *(uint4*)(g_wihtf + i) = o;
}

// ---- K1c: h0 -> tf32 buffer 0, reset barrier flags + sums --------------------
__global__ void k_h0(const float* __restrict__ h0) {
    int i = blockIdx.x * 256 + threadIdx.x;
    g_htf[0][i] = f2tf(h0[i]);
    if (i < cM) g_sum[i] = 0.f;
    if (i < NCTA * 32) g_flags[i] = 0;
}

// ---- K2: gi = X @ w_ih^T + b_ih (tf32, operands pre-converted) ---------------
__global__ __launch_bounds__(128) void k_gi(const float* __restrict__ bih) {
    constexpr int PAD = 20;
    __shared__ unsigned sA[2][64 * PAD], sB[2][64 * PAD];
    const int m0 = blockIdx.x * 64, n0 = blockIdx.y * 64;
    const int tid = threadIdx.x, lane = tid & 31;
    const int w = tid >> 5, wm = w & 1, wn = w >> 1;
    const int g = lane >> 2, q = lane & 3;
    float acc[2][4][4];
#pragma unroll
    for (int a = 0; a < 2; a++)
#pragma unroll
        for (int b = 0; b < 4; b++)
#pragma unroll
            for (int c = 0; c < 4; c++) acc[a][b][c] = 0.f;
    uint4 ra[2], rb[2];
    auto loadG = [&](int kc) {
#pragma unroll
        for (int j = 0; j < 2; ++j) {
            int f = tid * 2 + j, row = f >> 2, c = (f & 3) * 4;
            ra[j] = *(const uint4*)(g_X + (size_t)(m0 + row) * cH + kc + c);
            rb[j] = *(const uint4*)(g_wihtf + (size_t)(n0 + row) * cH + kc + c);
        }
    };
    auto storeS = [&](int buf) {
#pragma unroll
        for (int j = 0; j < 2; ++j) {
            int f = tid * 2 + j, row = f >> 2, c = (f & 3) * 4;
            *(uint4*)&sA[buf][row * PAD + c] = ra[j];
            *(uint4*)&sB[buf][row * PAD + c] = rb[j];
        }
    };
    loadG(0); storeS(0); __syncthreads();
    constexpr int NC = cH / 16;
    for (int ch = 0; ch < NC; ++ch) {
        int cur = ch & 1;
        if (ch + 1 < NC) loadG((ch + 1) * 16);
#pragma unroll
        for (int kt = 0; kt < 2; ++kt) {
            int kk = kt * 8;
            unsigned a[2][4];
#pragma unroll
            for (int mt = 0; mt < 2; ++mt) {
                int r = wm * 32 + mt * 16 + g;
                a[mt][0] = sA[cur][r * PAD + kk + q];
                a[mt][1] = sA[cur][(r + 8) * PAD + kk + q];
                a[mt][2] = sA[cur][r * PAD + kk + q + 4];
                a[mt][3] = sA[cur][(r + 8) * PAD + kk + q + 4];
            }
#pragma unroll
            for (int nt = 0; nt < 4; ++nt) {
                int c = wn * 32 + nt * 8 + g;
                unsigned b0 = sB[cur][c * PAD + kk + q];
                unsigned b1 = sB[cur][c * PAD + kk + q + 4];
                mma_tf32(acc[0][nt], a[0], b0, b1);
                mma_tf32(acc[1][nt], a[1], b0, b1);
            }
        }
        if (ch + 1 < NC) { storeS((ch + 1) & 1); __syncthreads(); }
    }
#pragma unroll
    for (int mt = 0; mt < 2; ++mt)
#pragma unroll
        for (int nt = 0; nt < 4; ++nt) {
            int row = m0 + wm * 32 + mt * 16 + g;
            int col = n0 + wn * 32 + nt * 8 + 2 * q;
            float b0 = bih[col], b1 = bih[col + 1];
            g_gi[(size_t)row * cG + col]           = acc[mt][nt][0] + b0;
            g_gi[(size_t)row * cG + col + 1]       = acc[mt][nt][1] + b1;
            g_gi[(size_t)(row + 8) * cG + col]     = acc[mt][nt][2] + b0;
            g_gi[(size_t)(row + 8) * cG + col + 1] = acc[mt][nt][3] + b1;
        }
}

// ---- K3: persistent GRU recurrence (tf32) ------------------------------------
constexpr int WSTR = 1028;
constexpr int HSTR = 132;

__global__ __launch_bounds__(RTHREADS) void k_rnn(const float* __restrict__ h0,
                                                  const float* __restrict__ Whh,
                                                  const float* __restrict__ bhh,
                                                  float* __restrict__ outh) {
    extern __shared__ unsigned su[];
    unsigned* w_s  = su;                        // 24 * WSTR
    unsigned* h_s  = w_s + 24 * WSTR;           // 2 * 32 * HSTR
    float*    sGH  = (float*)(h_s + 2 * 32 * HSTR);
    float*    h_own = sGH + 3 * 32 * 9;
    float*    bhh_s = h_own + 32 * 8;

    const int tid = threadIdx.x, lane = tid & 31, w = tid >> 5;
    const int g = lane >> 2, q = lane & 3;
    const int u0 = blockIdx.x * UPC;

    for (int i = tid; i < 24 * 256; i += RTHREADS) {
        int r = i >> 8, c4 = (i & 255) * 4;
        int gate = r >> 3, rr = r & 7;
        float4 v = *(const float4*)(Whh + ((size_t)gate * cH + u0 + rr) * cH + c4);
        unsigned* p = &w_s[r * WSTR + c4];
        p[0] = f2tf(v.x); p[1] = f2tf(v.y); p[2] = f2tf(v.z); p[3] = f2tf(v.w);
    }
    if (tid < 24) bhh_s[tid] = bhh[(tid >> 3) * cH + u0 + (tid & 7)];
    for (int i = tid; i < 32 * 8; i += RTHREADS)
        h_own[i] = h0[(i >> 3) * cH + u0 + (i & 7)];
    __syncthreads();

    for (int t = 0; t < cT; ++t) {
        float gr[3], gz[3], gn[3];
#pragma unroll
        for (int j = 0; j < 3; ++j) {
            int idx = tid + 96 * j;
            if (idx < 256) {
                int b = idx >> 3, u = idx & 7;
                const float* gi = g_gi + ((size_t)t * cB + b) * cG + u0 + u;
                gr[j] = gi[0]; gz[j] = gi[cH]; gn[j] = gi[2 * cH];
            }
        }
        const unsigned* hsrc = g_htf[t & 1];
        auto ldchunk = [&](int ki, int buf) {
            int kc = ki * 128;
            for (int i = tid; i < 1024; i += RTHREADS) {
                int r = i >> 5, c4 = (i & 31) * 4;
                cpasync16(smem_u32(&h_s[buf * 32 * HSTR + r * HSTR + c4]), hsrc + r * cH + kc + c4);
            }
            asm volatile("cp.async.commit_group;\n");
        };
        ldchunk(0, 0);
        float acc[2][4] = {{0.f,0.f,0.f,0.f},{0.f,0.f,0.f,0.f}};
        for (int ki = 0; ki < 8; ++ki) {
            if (ki + 1 < 8) { ldchunk(ki + 1, (ki + 1) & 1); asm volatile("cp.async.wait_group 1;\n"); }
            else           { asm volatile("cp.async.wait_group 0;\n"); }
            __syncthreads();
            const unsigned* hb = &h_s[(ki & 1) * 32 * HSTR];
            const unsigned* wb = &w_s[w * 8 * WSTR + ki * 128];
#pragma unroll
            for (int kk = 0; kk < 16; ++kk) {
                int kcol = kk * 8;
                unsigned b0 = wb[g * WSTR + kcol + q];
                unsigned b1 = wb[g * WSTR + kcol + q + 4];
#pragma unroll
                for (int mt = 0; mt < 2; ++mt) {
                    unsigned a[4];
                    a[0] = hb[(mt * 16 + g) * HSTR + kcol + q];
                    a[1] = hb[(mt * 16 + g + 8) * HSTR + kcol + q];
                    a[2] = hb[(mt * 16 + g) * HSTR + kcol + q + 4];
                    a[3] = hb[(mt * 16 + g + 8) * HSTR + kcol + q + 4];
                    mma_tf32(acc[mt], a, b0, b1);
                }
            }
            __syncthreads();
        }
        float* sg = sGH + w * (32 * 9);
#pragma unroll
        for (int mt = 0; mt < 2; ++mt) {
            sg[(mt * 16 + g) * 9 + 2 * q]         = acc[mt][0];
            sg[(mt * 16 + g) * 9 + 2 * q + 1]     = acc[mt][1];
            sg[(mt * 16 + g + 8) * 9 + 2 * q]     = acc[mt][2];
            sg[(mt * 16 + g + 8) * 9 + 2 * q + 1] = acc[mt][3];
        }
        __syncthreads();
#pragma unroll
        for (int j = 0; j < 3; ++j) {
            int idx = tid + 96 * j;
            if (idx < 256) {
                int b = idx >> 3, u = idx & 7;
                float pr = gr[j] + sGH[0 * 288 + b * 9 + u] + bhh_s[u];
                float pz = gz[j] + sGH[1 * 288 + b * 9 + u] + bhh_s[8 + u];
                float hn = sGH[2 * 288 + b * 9 + u] + bhh_s[16 + u];
                float r = 1.f / (1.f + expf(-pr));
                float z = 1.f / (1.f + expf(-pz));
                float n = tanhf(gn[j] + r * hn);
                float hv = (1.f - z) * n + z * h_own[idx];
                h_own[idx] = hv;
                g_htf[(t + 1) & 1][b * cH + u0 + u] = f2tf(hv);
                g_hsb[((size_t)b * cT + t) * cH + u0 + u] = __float2bfloat16(hv);
                if (t == cT - 1) outh[b * cH + u0 + u] = hv;
            }
        }
        __threadfence();
        __syncthreads();
        if (tid == 0) ((volatile unsigned*)g_flags)[blockIdx.x * 32] = t + 1;
        {
            int s0 = tid;
            while (((volatile unsigned*)g_flags)[s0 * 32] < (unsigned)(t + 1)) { }
            if (tid < NCTA - 96) {
                int s1 = tid + 96;
                while (((volatile unsigned*)g_flags)[s1 * 32] < (unsigned)(t + 1)) { }
            }
        }
        __syncthreads();
        __threadfence();
    }
}

// ---- K4: logits GEMM (bf16 HMMA, 128x128 tile, cp.async 3-stage + ldmatrix) --
constexpr int LKCH = 64;                  // k cols per stage
constexpr int LPAD = 72;                  // element stride (144B, conflict-free)
constexpr int LSTG = 128 * LPAD * 2;      // 18432 B per operand-stage
constexpr int LSM_TOT = 6 * LSTG + 1024;  // 3 A + 3 B stages + srow/sbias

__global__ __launch_bounds__(256) void k_logits(const float* __restrict__ bout,
                                                float* __restrict__ out) {
    extern __shared__ char sm[];
    const unsigned smb = smem_u32(sm);
    const unsigned aBase = smb, bBase = smb + 3 * LSTG;
    float* srow  = (float*)(sm + 6 * LSTG);
    float* sbias = srow + 128;
    const int m0 = blockIdx.x * 128, n0 = blockIdx.y * 128;
    const int tid = threadIdx.x, lane = tid & 31;
    const int w = tid >> 5, wm = w & 1, wn = w >> 1;   // 2 (m) x 4 (n) warps
    const int g = lane >> 2, q = lane & 3;
    const int lr = lane & 7, lh = (lane >> 3) & 1, lq = lane >> 4;
    const int arow = lr + lh * 8, acol = lq * 8;
    const int brow = lr + lq * 8, bcol = lh * 8;

    if (tid < 128) { srow[tid] = 0.f; sbias[tid] = bout[n0 + tid]; }

    float acc[4][4][4];
#pragma unroll
    for (int a = 0; a < 4; a++)
#pragma unroll
        for (int b = 0; b < 4; b++)
#pragma unroll
            for (int c = 0; c < 4; c++) acc[a][b][c] = 0.f;

    auto loadStage = [&](int s) {
        int buf = s % 3;
        const char* asrc = (const char*)(g_hsb + (size_t)m0 * cH + s * LKCH);
        const char* bsrc = (const char*)(g_wob + (size_t)n0 * cH + s * LKCH);
        unsigned ad = aBase + buf * LSTG, bd = bBase + buf * LSTG;
#pragma unroll
        for (int j = 0; j < 4; ++j) {         // 1024 x 16B per operand
            int i = tid + 256 * j;
            int row = i >> 3, cb = (i & 7) * 16;
            cpasync16(ad + row * (LPAD * 2) + cb, asrc + (size_t)row * (cH * 2) + cb);
            cpasync16(bd + row * (LPAD * 2) + cb, bsrc + (size_t)row * (cH * 2) + cb);
        }
        asm volatile("cp.async.commit_group;\n");
    };

    loadStage(0); loadStage(1);
    constexpr int NS = cH / LKCH;   // 16
    for (int s = 0; s < NS; ++s) {
        if (s == NS - 1) asm volatile("cp.async.wait_group 0;\n");
        else             asm volatile("cp.async.wait_group 1;\n");
        __syncthreads();
        int buf = s % 3;
        unsigned aS = aBase + buf * LSTG, bS = bBase + buf * LSTG;
#pragma unroll
        for (int kt = 0; kt < 4; ++kt) {
            int kk = kt * 16;
            unsigned a[4][4], bf[2][4];
#pragma unroll
            for (int mt = 0; mt < 4; ++mt)
                ldmat4(a[mt], aS + (((wm * 64 + mt * 16 + arow) * LPAD + kk + acol) << 1));
#pragma unroll
            for (int p = 0; p < 2; ++p)
                ldmat4(bf[p], bS + (((wn * 32 + p * 16 + brow) * LPAD + kk + bcol) << 1));
#pragma unroll
            for (int nt = 0; nt < 4; ++nt) {
                unsigned b0 = bf[nt >> 1][(nt & 1) * 2];
                unsigned b1 = bf[nt >> 1][(nt & 1) * 2 + 1];
#pragma unroll
                for (int mt = 0; mt < 4; ++mt)
                    mma_bf16(acc[mt][nt], a[mt], b0, b1);
            }
        }
        if (s + 2 < NS) loadStage(s + 2);
    }

    // epilogue: bias + store + exp partial sums
    float es[4][2];
#pragma unroll
    for (int mt = 0; mt < 4; ++mt) { es[mt][0] = 0.f; es[mt][1] = 0.f; }
#pragma unroll
    for (int mt = 0; mt < 4; ++mt)
#pragma unroll
        for (int nt = 0; nt < 4; ++nt) {
            int row = m0 + wm * 64 + mt * 16 + g;
            int lc  = wn * 32 + nt * 8 + 2 * q;
            int col = n0 + lc;
            float v0 = acc[mt][nt][0] + sbias[lc];
            float v1 = acc[mt][nt][1] + sbias[lc + 1];
            float v2 = acc[mt][nt][2] + sbias[lc];
            float v3 = acc[mt][nt][3] + sbias[lc + 1];
            out[(size_t)row * cV + col]           = v0;
            out[(size_t)row * cV + col + 1]       = v1;
            out[(size_t)(row + 8) * cV + col]     = v2;
            out[(size_t)(row + 8) * cV + col + 1] = v3;
            es[mt][0] += __expf(v0) + __expf(v1);
            es[mt][1] += __expf(v2) + __expf(v3);
        }
#pragma unroll
    for (int mt = 0; mt < 4; ++mt)
#pragma unroll
        for (int h = 0; h < 2; ++h) {
            es[mt][h] += __shfl_xor_sync(0xFFFFFFFFu, es[mt][h], 1);
            es[mt][h] += __shfl_xor_sync(0xFFFFFFFFu, es[mt][h], 2);
        }
    if (q == 0) {
#pragma unroll
        for (int mt = 0; mt < 4; ++mt) {
            atomicAdd(&srow[wm * 64 + mt * 16 + g], es[mt][0]);
            atomicAdd(&srow[wm * 64 + mt * 16 + g + 8], es[mt][1]);
        }
    }
    __syncthreads();
    if (tid < 128) atomicAdd(&g_sum[m0 + tid], srow[tid]);
}

// ---- K6: subtract log(sum) in-place (8 CTAs per row) -------------------------
__global__ __launch_bounds__(256) void k_sub(float* __restrict__ out) {
    int row = blockIdx.x;
    float l = logf(g_sum[row]);
    const int seg = blockIdx.y;              // 0..7, 4000 elems each
    float4* p = (float4*)(out + (size_t)row * cV + seg * 4000);
    for (int i = threadIdx.x; i < 1000; i += 256) {
        float4 v = p[i];
        v.x -= l; v.y -= l; v.z -= l; v.w -= l;
        p[i] = v;
    }
}

extern "C" void kernel_launch(void* const* d_in, const int* in_sizes, int n_in,
                              void* d_out, int out_size) {
    const float* enc_hidden = (const float*)d_in[1];
    const int*   target     = (const int*)d_in[2];
    const float* emb        = (const float*)d_in[3];
    const float* w_ih       = (const float*)d_in[4];
    const float* w_hh       = (const float*)d_in[5];
    const float* b_ih       = (const float*)d_in[6];
    const float* b_hh       = (const float*)d_in[7];
    const float* w_out      = (const float*)d_in[8];
    const float* b_out      = (const float*)d_in[9];
    float* out = (float*)d_out;

    constexpr int RSMEM = (24 * WSTR + 2 * 32 * HSTR) * 4 + (3 * 32 * 9 + 32 * 8 + 24) * 4;
    cudaFuncSetAttribute(k_rnn, cudaFuncAttributeMaxDynamicSharedMemorySize, RSMEM);
    cudaFuncSetAttribute(k_logits, cudaFuncAttributeMaxDynamicSharedMemorySize, LSM_TOT);

    k_embed<<<cM, 256>>>(target, emb);
    k_cvt_wout<<<cV, 256>>>(w_out);
    k_cvt_wih<<<cG, 256>>>(w_ih);
    k_h0<<<cB * cH / 256, 256>>>(enc_hidden);
    k_gi<<<dim3(cM / 64, cG / 64), 128>>>(b_ih);
    k_rnn<<<NCTA, RTHREADS, RSMEM>>>(enc_hidden, w_hh, b_hh, out + cBTV);
    k_logits<<<dim3(cM / 128, cV / 128), 256, LSM_TOT>>>(b_out, out);
    k_sub<<<dim3(cM, 8), 256>>>(out);
}

// round 10
// speedup vs baseline: 2.1333x; 1.0726x over previous
#include <cuda_runtime.h>
#include <cuda_bf16.h>
#include <cstdint>

constexpr int cV = 32000, cH = 1024, cB = 32, cT = 64;
constexpr int cM = cB * cT;           // 2048
constexpr int cG = 3 * cH;            // 3072
constexpr long long cBTV = (long long)cB * cT * cV;

constexpr int NCTA = 128;             // recurrence CTAs
constexpr int UPC  = 8;               // hidden units per CTA
constexpr int RTHREADS = 96;

__device__ __align__(16) unsigned      g_X[cM * cH];             // tf32 relu(embed)
__device__ __align__(16) unsigned      g_wihtf[(size_t)cG * cH]; // tf32 w_ih
__device__ __align__(16) float         g_gi[(size_t)cM * cG];
__device__ __align__(16) unsigned      g_htf[2][cB * cH];        // tf32 h ping-pong
__device__ __align__(16) __nv_bfloat16 g_hsb[cM * cH];           // [b*T+t][H]
__device__ __align__(16) __nv_bfloat16 g_wob[(size_t)cV * cH];
__device__ float g_sum[cM];
__device__ unsigned g_flags[NCTA * 32];   // 128B-strided barrier slots

__device__ __forceinline__ unsigned f2tf(float f) {
    unsigned u; asm("cvt.rna.tf32.f32 %0, %1;" : "=r"(u) : "f"(f)); return u;
}
__device__ __forceinline__ unsigned smem_u32(const void* p) {
    unsigned a;
    asm("{ .reg .u64 t; cvta.to.shared.u64 t, %1; cvt.u32.u64 %0, t; }" : "=r"(a) : "l"(p));
    return a;
}
__device__ __forceinline__ void mma_tf32(float* c, const unsigned* a, unsigned b0, unsigned b1) {
    asm volatile("mma.sync.aligned.m16n8k8.row.col.f32.tf32.tf32.f32 "
        "{%0,%1,%2,%3}, {%4,%5,%6,%7}, {%8,%9}, {%0,%1,%2,%3};\n"
        : "+f"(c[0]), "+f"(c[1]), "+f"(c[2]), "+f"(c[3])
        : "r"(a[0]), "r"(a[1]), "r"(a[2]), "r"(a[3]), "r"(b0), "r"(b1));
}
__device__ __forceinline__ void mma_bf16(float* c, const unsigned* a, unsigned b0, unsigned b1) {
    asm volatile("mma.sync.aligned.m16n8k16.row.col.f32.bf16.bf16.f32 "
        "{%0,%1,%2,%3}, {%4,%5,%6,%7}, {%8,%9}, {%0,%1,%2,%3};\n"
        : "+f"(c[0]), "+f"(c[1]), "+f"(c[2]), "+f"(c[3])
        : "r"(a[0]), "r"(a[1]), "r"(a[2]), "r"(a[3]), "r"(b0), "r"(b1));
}
__device__ __forceinline__ void ldmat4(unsigned* r, unsigned addr) {
    asm volatile("ldmatrix.sync.aligned.m8n8.x4.shared.b16 {%0,%1,%2,%3}, [%4];"
        : "=r"(r[0]), "=r"(r[1]), "=r"(r[2]), "=r"(r[3]) : "r"(addr));
}
__device__ __forceinline__ void cpasync16(unsigned dst, const void* src) {
    asm volatile("cp.async.cg.shared.global [%0], [%1], 16;\n" :: "r"(dst), "l"(src));
}

// ---- K1a: relu(embedding[token]) -> g_X (tf32) -------------------------------
__global__ void k_embed(const int* __restrict__ target, const float* __restrict__ emb) {
    int m = blockIdx.x, t = m >> 5, b = m & 31;
    int tok = (t == 0) ? 1 : target[b * cT + (t - 1)];
    float4 v = ((const float4*)(emb + (size_t)tok * cH))[threadIdx.x];
    uint4 o;
    o.x = f2tf(fmaxf(v.x, 0.f)); o.y = f2tf(fmaxf(v.y, 0.f));
    o.z = f2tf(fmaxf(v.z, 0.f)); o.w = f2tf(fmaxf(v.w, 0.f));
    ((uint4*)(g_X + (size_t)m * cH))[threadIdx.x] = o;
}

// ---- K1b: w_out -> bf16 ------------------------------------------------------
__global__ void k_cvt_wout(const float* __restrict__ w) {
    size_t i = (size_t)blockIdx.x * 1024 + threadIdx.x * 4;
    float4 v = *(const float4*)(w + i);
    *(__nv_bfloat162*)(g_wob + i)     = __floats2bfloat162_rn(v.x, v.y);
    *(__nv_bfloat162*)(g_wob + i + 2) = __floats2bfloat162_rn(v.z, v.w);
}

// ---- K1d: w_ih -> tf32 -------------------------------------------------------
__global__ void k_cvt_wih(const float* __restrict__ w) {
    size_t i = (size_t)blockIdx.x * 1024 + threadIdx.x * 4;
    float4 v = *(const float4*)(w + i);
    uint4 o; o.x = f2tf(v.x); o.y = f2tf(v.y); o.z = f2tf(v.z); o.w = f2tf(v.w);
    *(uint4*)(g_wihtf + i) = o;
}

// ---- K1c: h0 -> tf32 buffer 0, reset barrier flags + sums --------------------
__global__ void k_h0(const float* __restrict__ h0) {
    int i = blockIdx.x * 256 + threadIdx.x;
    g_htf[0][i] = f2tf(h0[i]);
    if (i < cM) g_sum[i] = 0.f;
    if (i < NCTA * 32) g_flags[i] = 0;
}

// ---- K2: gi = X @ w_ih^T + b_ih (tf32, 128x128 tile, cp.async 3-stage) -------
constexpr int GKCH = 64;                   // k cols per stage
constexpr int GPAD = 68;                   // word stride (272B)
constexpr int GSTG = 128 * GPAD * 4;       // 34816 B per operand-stage
constexpr int GSM_TOT = 6 * GSTG + 16;

__global__ __launch_bounds__(256) void k_gi(const float* __restrict__ bih) {
    extern __shared__ char smg[];
    const unsigned smb = smem_u32(smg);
    const unsigned aBase = smb, bBase = smb + 3 * GSTG;
    const int m0 = blockIdx.x * 128, n0 = blockIdx.y * 128;
    const int tid = threadIdx.x, lane = tid & 31;
    const int w = tid >> 5, wm = w & 1, wn = w >> 1;   // 2 (m) x 4 (n)
    const int g = lane >> 2, q = lane & 3;

    float acc[4][4][4];
#pragma unroll
    for (int a = 0; a < 4; a++)
#pragma unroll
        for (int b = 0; b < 4; b++)
#pragma unroll
            for (int c = 0; c < 4; c++) acc[a][b][c] = 0.f;

    auto loadStage = [&](int s) {
        int buf = s % 3;
        const char* asrc = (const char*)(g_X + (size_t)m0 * cH + s * GKCH);
        const char* bsrc = (const char*)(g_wihtf + (size_t)n0 * cH + s * GKCH);
        unsigned ad = aBase + buf * GSTG, bd = bBase + buf * GSTG;
#pragma unroll
        for (int j = 0; j < 8; ++j) {          // 2048 x 16B per operand
            int i = tid + 256 * j;
            int row = i >> 4, cb = (i & 15) * 16;
            cpasync16(ad + row * (GPAD * 4) + cb, asrc + (size_t)row * (cH * 4) + cb);
            cpasync16(bd + row * (GPAD * 4) + cb, bsrc + (size_t)row * (cH * 4) + cb);
        }
        asm volatile("cp.async.commit_group;\n");
    };

    loadStage(0); loadStage(1);
    constexpr int NS = cH / GKCH;   // 16
    for (int s = 0; s < NS; ++s) {
        if (s == NS - 1) asm volatile("cp.async.wait_group 0;\n");
        else             asm volatile("cp.async.wait_group 1;\n");
        __syncthreads();
        if (s + 2 < NS) loadStage(s + 2);
        int buf = s % 3;
        const unsigned* aS = (const unsigned*)(smg + buf * GSTG);
        const unsigned* bS = (const unsigned*)(smg + 3 * GSTG + buf * GSTG);
#pragma unroll
        for (int kt = 0; kt < 8; ++kt) {
            int kk = kt * 8;
            unsigned a[4][4];
#pragma unroll
            for (int mt = 0; mt < 4; ++mt) {
                int r = wm * 64 + mt * 16 + g;
                a[mt][0] = aS[r * GPAD + kk + q];
                a[mt][1] = aS[(r + 8) * GPAD + kk + q];
                a[mt][2] = aS[r * GPAD + kk + q + 4];
                a[mt][3] = aS[(r + 8) * GPAD + kk + q + 4];
            }
#pragma unroll
            for (int nt = 0; nt < 4; ++nt) {
                int c = wn * 32 + nt * 8 + g;
                unsigned b0 = bS[c * GPAD + kk + q];
                unsigned b1 = bS[c * GPAD + kk + q + 4];
#pragma unroll
                for (int mt = 0; mt < 4; ++mt)
                    mma_tf32(acc[mt][nt], a[mt], b0, b1);
            }
        }
    }
#pragma unroll
    for (int mt = 0; mt < 4; ++mt)
#pragma unroll
        for (int nt = 0; nt < 4; ++nt) {
            int row = m0 + wm * 64 + mt * 16 + g;
            int col = n0 + wn * 32 + nt * 8 + 2 * q;
            float b0 = bih[col], b1 = bih[col + 1];
            g_gi[(size_t)row * cG + col]           = acc[mt][nt][0] + b0;
            g_gi[(size_t)row * cG + col + 1]       = acc[mt][nt][1] + b1;
            g_gi[(size_t)(row + 8) * cG + col]     = acc[mt][nt][2] + b0;
            g_gi[(size_t)(row + 8) * cG + col + 1] = acc[mt][nt][3] + b1;
        }
}

// ---- K3: persistent GRU recurrence (tf32, 256-col chunks, 3-buf ring) --------
constexpr int WSTR = 1028;
constexpr int HSTR = 260;     // 256 + 4 pad words

__global__ __launch_bounds__(RTHREADS) void k_rnn(const float* __restrict__ h0,
                                                  const float* __restrict__ Whh,
                                                  const float* __restrict__ bhh,
                                                  float* __restrict__ outh) {
    extern __shared__ unsigned su[];
    unsigned* w_s  = su;                        // 24 * WSTR
    unsigned* h_s  = w_s + 24 * WSTR;           // 3 * 32 * HSTR
    float*    sGH  = (float*)(h_s + 3 * 32 * HSTR);
    float*    h_own = sGH + 3 * 32 * 9;
    float*    bhh_s = h_own + 32 * 8;

    const int tid = threadIdx.x, lane = tid & 31, w = tid >> 5;
    const int g = lane >> 2, q = lane & 3;
    const int u0 = blockIdx.x * UPC;

    for (int i = tid; i < 24 * 256; i += RTHREADS) {
        int r = i >> 8, c4 = (i & 255) * 4;
        int gate = r >> 3, rr = r & 7;
        float4 v = *(const float4*)(Whh + ((size_t)gate * cH + u0 + rr) * cH + c4);
        unsigned* p = &w_s[r * WSTR + c4];
        p[0] = f2tf(v.x); p[1] = f2tf(v.y); p[2] = f2tf(v.z); p[3] = f2tf(v.w);
    }
    if (tid < 24) bhh_s[tid] = bhh[(tid >> 3) * cH + u0 + (tid & 7)];
    for (int i = tid; i < 32 * 8; i += RTHREADS)
        h_own[i] = h0[(i >> 3) * cH + u0 + (i & 7)];
    __syncthreads();

    for (int t = 0; t < cT; ++t) {
        float gr[3], gz[3], gn[3];
#pragma unroll
        for (int j = 0; j < 3; ++j) {
            int idx = tid + 96 * j;
            if (idx < 256) {
                int b = idx >> 3, u = idx & 7;
                const float* gi = g_gi + ((size_t)t * cB + b) * cG + u0 + u;
                gr[j] = gi[0]; gz[j] = gi[cH]; gn[j] = gi[2 * cH];
            }
        }
        const unsigned* hsrc = g_htf[t & 1];
        auto ldchunk = [&](int ki) {
            int buf = ki % 3, kc = ki * 256;
            for (int i = tid; i < 2048; i += RTHREADS) {   // 32 rows x 64 uint4
                int r = i >> 6, c4 = (i & 63) * 4;
                cpasync16(smem_u32(&h_s[buf * 32 * HSTR + r * HSTR + c4]),
                          hsrc + r * cH + kc + c4);
            }
            asm volatile("cp.async.commit_group;\n");
        };
        ldchunk(0); ldchunk(1);
        float acc[2][4] = {{0.f,0.f,0.f,0.f},{0.f,0.f,0.f,0.f}};
        for (int ki = 0; ki < 4; ++ki) {
            if (ki == 3) asm volatile("cp.async.wait_group 0;\n");
            else         asm volatile("cp.async.wait_group 1;\n");
            __syncthreads();
            if (ki + 2 < 4) ldchunk(ki + 2);
            const unsigned* hb = &h_s[(ki % 3) * 32 * HSTR];
            const unsigned* wb = &w_s[w * 8 * WSTR + ki * 256];
#pragma unroll
            for (int kk = 0; kk < 32; ++kk) {
                int kcol = kk * 8;
                unsigned b0 = wb[g * WSTR + kcol + q];
                unsigned b1 = wb[g * WSTR + kcol + q + 4];
#pragma unroll
                for (int mt = 0; mt < 2; ++mt) {
                    unsigned a[4];
                    a[0] = hb[(mt * 16 + g) * HSTR + kcol + q];
                    a[1] = hb[(mt * 16 + g + 8) * HSTR + kcol + q];
                    a[2] = hb[(mt * 16 + g) * HSTR + kcol + q + 4];
                    a[3] = hb[(mt * 16 + g + 8) * HSTR + kcol + q + 4];
                    mma_tf32(acc[mt], a, b0, b1);
                }
            }
        }
        __syncthreads();
        float* sg = sGH + w * (32 * 9);
#pragma unroll
        for (int mt = 0; mt < 2; ++mt) {
            sg[(mt * 16 + g) * 9 + 2 * q]         = acc[mt][0];
            sg[(mt * 16 + g) * 9 + 2 * q + 1]     = acc[mt][1];
            sg[(mt * 16 + g + 8) * 9 + 2 * q]     = acc[mt][2];
            sg[(mt * 16 + g + 8) * 9 + 2 * q + 1] = acc[mt][3];
        }
        __syncthreads();
#pragma unroll
        for (int j = 0; j < 3; ++j) {
            int idx = tid + 96 * j;
            if (idx < 256) {
                int b = idx >> 3, u = idx & 7;
                float pr = gr[j] + sGH[0 * 288 + b * 9 + u] + bhh_s[u];
                float pz = gz[j] + sGH[1 * 288 + b * 9 + u] + bhh_s[8 + u];
                float hn = sGH[2 * 288 + b * 9 + u] + bhh_s[16 + u];
                float r = 1.f / (1.f + expf(-pr));
                float z = 1.f / (1.f + expf(-pz));
                float n = tanhf(gn[j] + r * hn);
                float hv = (1.f - z) * n + z * h_own[idx];
                h_own[idx] = hv;
                g_htf[(t + 1) & 1][b * cH + u0 + u] = f2tf(hv);
                g_hsb[((size_t)b * cT + t) * cH + u0 + u] = __float2bfloat16(hv);
                if (t == cT - 1) outh[b * cH + u0 + u] = hv;
            }
        }
        __threadfence();
        __syncthreads();
        if (tid == 0) ((volatile unsigned*)g_flags)[blockIdx.x * 32] = t + 1;
        {
            int s0 = tid;
            while (((volatile unsigned*)g_flags)[s0 * 32] < (unsigned)(t + 1)) { }
            if (tid < NCTA - 96) {
                int s1 = tid + 96;
                while (((volatile unsigned*)g_flags)[s1 * 32] < (unsigned)(t + 1)) { }
            }
        }
        __syncthreads();
        __threadfence();
    }
}

// ---- K4: logits GEMM (bf16 HMMA, 128x128 tile, cp.async 3-stage + ldmatrix) --
constexpr int LKCH = 64;                  // k cols per stage
constexpr int LPAD = 72;                  // element stride (144B, conflict-free)
constexpr int LSTG = 128 * LPAD * 2;      // 18432 B per operand-stage
constexpr int LSM_TOT = 6 * LSTG + 1024;  // 3 A + 3 B stages + srow/sbias

__global__ __launch_bounds__(256) void k_logits(const float* __restrict__ bout,
                                                float* __restrict__ out) {
    extern __shared__ char sm[];
    const unsigned smb = smem_u32(sm);
    const unsigned aBase = smb, bBase = smb + 3 * LSTG;
    float* srow  = (float*)(sm + 6 * LSTG);
    float* sbias = srow + 128;
    const int m0 = blockIdx.x * 128, n0 = blockIdx.y * 128;
    const int tid = threadIdx.x, lane = tid & 31;
    const int w = tid >> 5, wm = w & 1, wn = w >> 1;   // 2 (m) x 4 (n) warps
    const int g = lane >> 2, q = lane & 3;
    const int lr = lane & 7, lh = (lane >> 3) & 1, lq = lane >> 4;
    const int arow = lr + lh * 8, acol = lq * 8;
    const int brow = lr + lq * 8, bcol = lh * 8;

    if (tid < 128) { srow[tid] = 0.f; sbias[tid] = bout[n0 + tid]; }

    float acc[4][4][4];
#pragma unroll
    for (int a = 0; a < 4; a++)
#pragma unroll
        for (int b = 0; b < 4; b++)
#pragma unroll
            for (int c = 0; c < 4; c++) acc[a][b][c] = 0.f;

    auto loadStage = [&](int s) {
        int buf = s % 3;
        const char* asrc = (const char*)(g_hsb + (size_t)m0 * cH + s * LKCH);
        const char* bsrc = (const char*)(g_wob + (size_t)n0 * cH + s * LKCH);
        unsigned ad = aBase + buf * LSTG, bd = bBase + buf * LSTG;
#pragma unroll
        for (int j = 0; j < 4; ++j) {         // 1024 x 16B per operand
            int i = tid + 256 * j;
            int row = i >> 3, cb = (i & 7) * 16;
            cpasync16(ad + row * (LPAD * 2) + cb, asrc + (size_t)row * (cH * 2) + cb);
            cpasync16(bd + row * (LPAD * 2) + cb, bsrc + (size_t)row * (cH * 2) + cb);
        }
        asm volatile("cp.async.commit_group;\n");
    };

    loadStage(0); loadStage(1);
    constexpr int NS = cH / LKCH;   // 16
    for (int s = 0; s < NS; ++s) {
        if (s == NS - 1) asm volatile("cp.async.wait_group 0;\n");
        else             asm volatile("cp.async.wait_group 1;\n");
        __syncthreads();
        if (s + 2 < NS) loadStage(s + 2);
        int buf = s % 3;
        unsigned aS = aBase + buf * LSTG, bS = bBase + buf * LSTG;
#pragma unroll
        for (int kt = 0; kt < 4; ++kt) {
            int kk = kt * 16;
            unsigned a[4][4], bf[2][4];
#pragma unroll
            for (int mt = 0; mt < 4; ++mt)
                ldmat4(a[mt], aS + (((wm * 64 + mt * 16 + arow) * LPAD + kk + acol) << 1));
#pragma unroll
            for (int p = 0; p < 2; ++p)
                ldmat4(bf[p], bS + (((wn * 32 + p * 16 + brow) * LPAD + kk + bcol) << 1));
#pragma unroll
            for (int nt = 0; nt < 4; ++nt) {
                unsigned b0 = bf[nt >> 1][(nt & 1) * 2];
                unsigned b1 = bf[nt >> 1][(nt & 1) * 2 + 1];
#pragma unroll
                for (int mt = 0; mt < 4; ++mt)
                    mma_bf16(acc[mt][nt], a[mt], b0, b1);
            }
        }
    }

    // epilogue: bias + store + exp partial sums
    float es[4][2];
#pragma unroll
    for (int mt = 0; mt < 4; ++mt) { es[mt][0] = 0.f; es[mt][1] = 0.f; }
#pragma unroll
    for (int mt = 0; mt < 4; ++mt)
#pragma unroll
        for (int nt = 0; nt < 4; ++nt) {
            int row = m0 + wm * 64 + mt * 16 + g;
            int lc  = wn * 32 + nt * 8 + 2 * q;
            int col = n0 + lc;
            float v0 = acc[mt][nt][0] + sbias[lc];
            float v1 = acc[mt][nt][1] + sbias[lc + 1];
            float v2 = acc[mt][nt][2] + sbias[lc];
            float v3 = acc[mt][nt][3] + sbias[lc + 1];
            out[(size_t)row * cV + col]           = v0;
            out[(size_t)row * cV + col + 1]       = v1;
            out[(size_t)(row + 8) * cV + col]     = v2;
            out[(size_t)(row + 8) * cV + col + 1] = v3;
            es[mt][0] += __expf(v0) + __expf(v1);
            es[mt][1] += __expf(v2) + __expf(v3);
        }
#pragma unroll
    for (int mt = 0; mt < 4; ++mt)
#pragma unroll
        for (int h = 0; h < 2; ++h) {
            es[mt][h] += __shfl_xor_sync(0xFFFFFFFFu, es[mt][h], 1);
            es[mt][h] += __shfl_xor_sync(0xFFFFFFFFu, es[mt][h], 2);
        }
    if (q == 0) {
#pragma unroll
        for (int mt = 0; mt < 4; ++mt) {
            atomicAdd(&srow[wm * 64 + mt * 16 + g], es[mt][0]);
            atomicAdd(&srow[wm * 64 + mt * 16 + g + 8], es[mt][1]);
        }
    }
    __syncthreads();
    if (tid < 128) atomicAdd(&g_sum[m0 + tid], srow[tid]);
}

// ---- K6: subtract log(sum) in-place (8 CTAs per row) -------------------------
__global__ __launch_bounds__(256) void k_sub(float* __restrict__ out) {
    int row = blockIdx.x;
    float l = logf(g_sum[row]);
    const int seg = blockIdx.y;              // 0..7, 4000 elems each
    float4* p = (float4*)(out + (size_t)row * cV + seg * 4000);
    for (int i = threadIdx.x; i < 1000; i += 256) {
        float4 v = p[i];
        v.x -= l; v.y -= l; v.z -= l; v.w -= l;
        p[i] = v;
    }
}

extern "C" void kernel_launch(void* const* d_in, const int* in_sizes, int n_in,
                              void* d_out, int out_size) {
    const float* enc_hidden = (const float*)d_in[1];
    const int*   target     = (const int*)d_in[2];
    const float* emb        = (const float*)d_in[3];
    const float* w_ih       = (const float*)d_in[4];
    const float* w_hh       = (const float*)d_in[5];
    const float* b_ih       = (const float*)d_in[6];
    const float* b_hh       = (const float*)d_in[7];
    const float* w_out      = (const float*)d_in[8];
    const float* b_out      = (const float*)d_in[9];
    float* out = (float*)d_out;

    constexpr int RSMEM = (24 * WSTR + 3 * 32 * HSTR) * 4 + (3 * 32 * 9 + 32 * 8 + 24) * 4;
    cudaFuncSetAttribute(k_rnn, cudaFuncAttributeMaxDynamicSharedMemorySize, RSMEM);
    cudaFuncSetAttribute(k_logits, cudaFuncAttributeMaxDynamicSharedMemorySize, LSM_TOT);
    cudaFuncSetAttribute(k_gi, cudaFuncAttributeMaxDynamicSharedMemorySize, GSM_TOT);

    k_embed<<<cM, 256>>>(target, emb);
    k_cvt_wout<<<cV, 256>>>(w_out);
    k_cvt_wih<<<cG, 256>>>(w_ih);
    k_h0<<<cB * cH / 256, 256>>>(enc_hidden);
    k_gi<<<dim3(cM / 128, cG / 128), 256, GSM_TOT>>>(b_ih);
    k_rnn<<<NCTA, RTHREADS, RSMEM>>>(enc_hidden, w_hh, b_hh, out + cBTV);
    k_logits<<<dim3(cM / 128, cV / 128), 256, LSM_TOT>>>(b_out, out);
    k_sub<<<dim3(cM, 8), 256>>>(out);
}

// round 11
// speedup vs baseline: 2.1512x; 1.0084x over previous
#include <cuda_runtime.h>
#include <cuda_bf16.h>
#include <cstdint>

constexpr int cV = 32000, cH = 1024, cB = 32, cT = 64;
constexpr int cM = cB * cT;           // 2048
constexpr int cG = 3 * cH;            // 3072
constexpr long long cBTV = (long long)cB * cT * cV;

constexpr int NCTA = 128;             // recurrence CTAs
constexpr int UPC  = 8;               // hidden units per CTA
constexpr int RTHREADS = 96;

__device__ __align__(16) unsigned      g_X[cM * cH];             // tf32 relu(embed)
__device__ __align__(16) unsigned      g_wihtf[(size_t)cG * cH]; // tf32 w_ih
__device__ __align__(16) float         g_gi[(size_t)cM * cG];
__device__ __align__(16) unsigned      g_htf[2][cB * cH];        // tf32 h ping-pong
__device__ __align__(16) __nv_bfloat16 g_hsb[cM * cH];           // [b*T+t][H]
__device__ __align__(16) __nv_bfloat16 g_wob[(size_t)cV * cH];
__device__ float g_sum[cM];
__device__ unsigned g_flags[NCTA * 32];   // 128B-strided barrier slots

__device__ __forceinline__ unsigned f2tf(float f) {
    unsigned u; asm("cvt.rna.tf32.f32 %0, %1;" : "=r"(u) : "f"(f)); return u;
}
__device__ __forceinline__ unsigned smem_u32(const void* p) {
    unsigned a;
    asm("{ .reg .u64 t; cvta.to.shared.u64 t, %1; cvt.u32.u64 %0, t; }" : "=r"(a) : "l"(p));
    return a;
}
__device__ __forceinline__ void mma_tf32(float* c, const unsigned* a, unsigned b0, unsigned b1) {
    asm volatile("mma.sync.aligned.m16n8k8.row.col.f32.tf32.tf32.f32 "
        "{%0,%1,%2,%3}, {%4,%5,%6,%7}, {%8,%9}, {%0,%1,%2,%3};\n"
        : "+f"(c[0]), "+f"(c[1]), "+f"(c[2]), "+f"(c[3])
        : "r"(a[0]), "r"(a[1]), "r"(a[2]), "r"(a[3]), "r"(b0), "r"(b1));
}
__device__ __forceinline__ void mma_bf16(float* c, const unsigned* a, unsigned b0, unsigned b1) {
    asm volatile("mma.sync.aligned.m16n8k16.row.col.f32.bf16.bf16.f32 "
        "{%0,%1,%2,%3}, {%4,%5,%6,%7}, {%8,%9}, {%0,%1,%2,%3};\n"
        : "+f"(c[0]), "+f"(c[1]), "+f"(c[2]), "+f"(c[3])
        : "r"(a[0]), "r"(a[1]), "r"(a[2]), "r"(a[3]), "r"(b0), "r"(b1));
}
__device__ __forceinline__ void ldmat4(unsigned* r, unsigned addr) {
    asm volatile("ldmatrix.sync.aligned.m8n8.x4.shared.b16 {%0,%1,%2,%3}, [%4];"
        : "=r"(r[0]), "=r"(r[1]), "=r"(r[2]), "=r"(r[3]) : "r"(addr));
}
__device__ __forceinline__ void cpasync16(unsigned dst, const void* src) {
    asm volatile("cp.async.cg.shared.global [%0], [%1], 16;\n" :: "r"(dst), "l"(src));
}

// ---- K0: fused preamble ------------------------------------------------------
// blocks [0, cV)               : w_out -> bf16
// blocks [cV, cV+cG)           : w_ih -> tf32
// blocks [cV+cG, cV+cG+cM)     : relu(embedding[token]) -> g_X
// blocks [cV+cG+cM, +cB*cH/256): h0 -> tf32, reset sums/flags
__global__ void k_pre(const int* __restrict__ target, const float* __restrict__ emb,
                      const float* __restrict__ w_out, const float* __restrict__ w_ih,
                      const float* __restrict__ h0) {
    int bx = blockIdx.x;
    if (bx < cV) {
        size_t i = (size_t)bx * 1024 + threadIdx.x * 4;
        float4 v = *(const float4*)(w_out + i);
        *(__nv_bfloat162*)(g_wob + i)     = __floats2bfloat162_rn(v.x, v.y);
        *(__nv_bfloat162*)(g_wob + i + 2) = __floats2bfloat162_rn(v.z, v.w);
    } else if (bx < cV + cG) {
        size_t i = (size_t)(bx - cV) * 1024 + threadIdx.x * 4;
        float4 v = *(const float4*)(w_ih + i);
        uint4 o; o.x = f2tf(v.x); o.y = f2tf(v.y); o.z = f2tf(v.z); o.w = f2tf(v.w);
        *(uint4*)(g_wihtf + i) = o;
    } else if (bx < cV + cG + cM) {
        int m = bx - cV - cG, t = m >> 5, b = m & 31;
        int tok = (t == 0) ? 1 : target[b * cT + (t - 1)];
        float4 v = ((const float4*)(emb + (size_t)tok * cH))[threadIdx.x];
        uint4 o;
        o.x = f2tf(fmaxf(v.x, 0.f)); o.y = f2tf(fmaxf(v.y, 0.f));
        o.z = f2tf(fmaxf(v.z, 0.f)); o.w = f2tf(fmaxf(v.w, 0.f));
        ((uint4*)(g_X + (size_t)m * cH))[threadIdx.x] = o;
    } else {
        int i = (bx - cV - cG - cM) * 256 + threadIdx.x;
        g_htf[0][i] = f2tf(h0[i]);
        if (i < cM) g_sum[i] = 0.f;
        if (i < NCTA * 32) g_flags[i] = 0;
    }
}

// ---- K2: gi = X @ w_ih^T + b_ih (tf32, 128x128 tile, 3-stage, 2 CTA/SM) ------
constexpr int GKCH = 32;                   // k cols per stage
constexpr int GPAD = 36;                   // word stride (144B)
constexpr int GSTG = 128 * GPAD * 4;       // 18432 B per operand-stage
constexpr int GSM_TOT = 6 * GSTG + 16;     // 110608 B

__global__ __launch_bounds__(256, 2) void k_gi(const float* __restrict__ bih) {
    extern __shared__ char smg[];
    const unsigned smb = smem_u32(smg);
    const unsigned aBase = smb, bBase = smb + 3 * GSTG;
    const int m0 = blockIdx.x * 128, n0 = blockIdx.y * 128;
    const int tid = threadIdx.x, lane = tid & 31;
    const int w = tid >> 5, wm = w & 1, wn = w >> 1;   // 2 (m) x 4 (n)
    const int g = lane >> 2, q = lane & 3;

    float acc[4][4][4];
#pragma unroll
    for (int a = 0; a < 4; a++)
#pragma unroll
        for (int b = 0; b < 4; b++)
#pragma unroll
            for (int c = 0; c < 4; c++) acc[a][b][c] = 0.f;

    auto loadStage = [&](int s) {
        int buf = s % 3;
        const char* asrc = (const char*)(g_X + (size_t)m0 * cH + s * GKCH);
        const char* bsrc = (const char*)(g_wihtf + (size_t)n0 * cH + s * GKCH);
        unsigned ad = aBase + buf * GSTG, bd = bBase + buf * GSTG;
#pragma unroll
        for (int j = 0; j < 4; ++j) {          // 1024 x 16B per operand
            int i = tid + 256 * j;
            int row = i >> 3, cb = (i & 7) * 16;
            cpasync16(ad + row * (GPAD * 4) + cb, asrc + (size_t)row * (cH * 4) + cb);
            cpasync16(bd + row * (GPAD * 4) + cb, bsrc + (size_t)row * (cH * 4) + cb);
        }
        asm volatile("cp.async.commit_group;\n");
    };

    loadStage(0); loadStage(1);
    constexpr int NS = cH / GKCH;   // 32
    for (int s = 0; s < NS; ++s) {
        if (s == NS - 1) asm volatile("cp.async.wait_group 0;\n");
        else             asm volatile("cp.async.wait_group 1;\n");
        __syncthreads();
        if (s + 2 < NS) loadStage(s + 2);
        int buf = s % 3;
        const unsigned* aS = (const unsigned*)(smg + buf * GSTG);
        const unsigned* bS = (const unsigned*)(smg + 3 * GSTG + buf * GSTG);
#pragma unroll
        for (int kt = 0; kt < 4; ++kt) {
            int kk = kt * 8;
            unsigned a[4][4];
#pragma unroll
            for (int mt = 0; mt < 4; ++mt) {
                int r = wm * 64 + mt * 16 + g;
                a[mt][0] = aS[r * GPAD + kk + q];
                a[mt][1] = aS[(r + 8) * GPAD + kk + q];
                a[mt][2] = aS[r * GPAD + kk + q + 4];
                a[mt][3] = aS[(r + 8) * GPAD + kk + q + 4];
            }
#pragma unroll
            for (int nt = 0; nt < 4; ++nt) {
                int c = wn * 32 + nt * 8 + g;
                unsigned b0 = bS[c * GPAD + kk + q];
                unsigned b1 = bS[c * GPAD + kk + q + 4];
#pragma unroll
                for (int mt = 0; mt < 4; ++mt)
                    mma_tf32(acc[mt][nt], a[mt], b0, b1);
            }
        }
    }
#pragma unroll
    for (int mt = 0; mt < 4; ++mt)
#pragma unroll
        for (int nt = 0; nt < 4; ++nt) {
            int row = m0 + wm * 64 + mt * 16 + g;
            int col = n0 + wn * 32 + nt * 8 + 2 * q;
            float b0 = bih[col], b1 = bih[col + 1];
            g_gi[(size_t)row * cG + col]           = acc[mt][nt][0] + b0;
            g_gi[(size_t)row * cG + col + 1]       = acc[mt][nt][1] + b1;
            g_gi[(size_t)(row + 8) * cG + col]     = acc[mt][nt][2] + b0;
            g_gi[(size_t)(row + 8) * cG + col + 1] = acc[mt][nt][3] + b1;
        }
}

// ---- K3: persistent GRU recurrence (tf32, 256-col chunks, 3-buf ring) --------
constexpr int WSTR = 1028;
constexpr int HSTR = 260;     // 256 + 4 pad words

__global__ __launch_bounds__(RTHREADS) void k_rnn(const float* __restrict__ h0,
                                                  const float* __restrict__ Whh,
                                                  const float* __restrict__ bhh,
                                                  float* __restrict__ outh) {
    extern __shared__ unsigned su[];
    unsigned* w_s  = su;                        // 24 * WSTR
    unsigned* h_s  = w_s + 24 * WSTR;           // 3 * 32 * HSTR
    float*    sGH  = (float*)(h_s + 3 * 32 * HSTR);
    float*    h_own = sGH + 3 * 32 * 9;
    float*    bhh_s = h_own + 32 * 8;

    const int tid = threadIdx.x, lane = tid & 31, w = tid >> 5;
    const int g = lane >> 2, q = lane & 3;
    const int u0 = blockIdx.x * UPC;

    for (int i = tid; i < 24 * 256; i += RTHREADS) {
        int r = i >> 8, c4 = (i & 255) * 4;
        int gate = r >> 3, rr = r & 7;
        float4 v = *(const float4*)(Whh + ((size_t)gate * cH + u0 + rr) * cH + c4);
        unsigned* p = &w_s[r * WSTR + c4];
        p[0] = f2tf(v.x); p[1] = f2tf(v.y); p[2] = f2tf(v.z); p[3] = f2tf(v.w);
    }
    if (tid < 24) bhh_s[tid] = bhh[(tid >> 3) * cH + u0 + (tid & 7)];
    for (int i = tid; i < 32 * 8; i += RTHREADS)
        h_own[i] = h0[(i >> 3) * cH + u0 + (i & 7)];
    __syncthreads();

    for (int t = 0; t < cT; ++t) {
        float gr[3], gz[3], gn[3];
#pragma unroll
        for (int j = 0; j < 3; ++j) {
            int idx = tid + 96 * j;
            if (idx < 256) {
                int b = idx >> 3, u = idx & 7;
                const float* gi = g_gi + ((size_t)t * cB + b) * cG + u0 + u;
                gr[j] = gi[0]; gz[j] = gi[cH]; gn[j] = gi[2 * cH];
            }
        }
        const unsigned* hsrc = g_htf[t & 1];
        auto ldchunk = [&](int ki) {
            int buf = ki % 3, kc = ki * 256;
            for (int i = tid; i < 2048; i += RTHREADS) {   // 32 rows x 64 uint4
                int r = i >> 6, c4 = (i & 63) * 4;
                cpasync16(smem_u32(&h_s[buf * 32 * HSTR + r * HSTR + c4]),
                          hsrc + r * cH + kc + c4);
            }
            asm volatile("cp.async.commit_group;\n");
        };
        ldchunk(0); ldchunk(1);
        float acc[2][4] = {{0.f,0.f,0.f,0.f},{0.f,0.f,0.f,0.f}};
        for (int ki = 0; ki < 4; ++ki) {
            if (ki == 3) asm volatile("cp.async.wait_group 0;\n");
            else         asm volatile("cp.async.wait_group 1;\n");
            __syncthreads();
            if (ki + 2 < 4) ldchunk(ki + 2);
            const unsigned* hb = &h_s[(ki % 3) * 32 * HSTR];
            const unsigned* wb = &w_s[w * 8 * WSTR + ki * 256];
#pragma unroll
            for (int kk = 0; kk < 32; ++kk) {
                int kcol = kk * 8;
                unsigned b0 = wb[g * WSTR + kcol + q];
                unsigned b1 = wb[g * WSTR + kcol + q + 4];
#pragma unroll
                for (int mt = 0; mt < 2; ++mt) {
                    unsigned a[4];
                    a[0] = hb[(mt * 16 + g) * HSTR + kcol + q];
                    a[1] = hb[(mt * 16 + g + 8) * HSTR + kcol + q];
                    a[2] = hb[(mt * 16 + g) * HSTR + kcol + q + 4];
                    a[3] = hb[(mt * 16 + g + 8) * HSTR + kcol + q + 4];
                    mma_tf32(acc[mt], a, b0, b1);
                }
            }
        }
        __syncthreads();
        float* sg = sGH + w * (32 * 9);
#pragma unroll
        for (int mt = 0; mt < 2; ++mt) {
            sg[(mt * 16 + g) * 9 + 2 * q]         = acc[mt][0];
            sg[(mt * 16 + g) * 9 + 2 * q + 1]     = acc[mt][1];
            sg[(mt * 16 + g + 8) * 9 + 2 * q]     = acc[mt][2];
            sg[(mt * 16 + g + 8) * 9 + 2 * q + 1] = acc[mt][3];
        }
        __syncthreads();
#pragma unroll
        for (int j = 0; j < 3; ++j) {
            int idx = tid + 96 * j;
            if (idx < 256) {
                int b = idx >> 3, u = idx & 7;
                float pr = gr[j] + sGH[0 * 288 + b * 9 + u] + bhh_s[u];
                float pz = gz[j] + sGH[1 * 288 + b * 9 + u] + bhh_s[8 + u];
                float hn = sGH[2 * 288 + b * 9 + u] + bhh_s[16 + u];
                float r = 1.f / (1.f + expf(-pr));
                float z = 1.f / (1.f + expf(-pz));
                float n = tanhf(gn[j] + r * hn);
                float hv = (1.f - z) * n + z * h_own[idx];
                h_own[idx] = hv;
                g_htf[(t + 1) & 1][b * cH + u0 + u] = f2tf(hv);
                g_hsb[((size_t)b * cT + t) * cH + u0 + u] = __float2bfloat16(hv);
                if (t == cT - 1) outh[b * cH + u0 + u] = hv;
            }
        }
        __threadfence();
        __syncthreads();
        if (tid == 0) ((volatile unsigned*)g_flags)[blockIdx.x * 32] = t + 1;
        {
            int s0 = tid;
            while (((volatile unsigned*)g_flags)[s0 * 32] < (unsigned)(t + 1)) { }
            if (tid < NCTA - 96) {
                int s1 = tid + 96;
                while (((volatile unsigned*)g_flags)[s1 * 32] < (unsigned)(t + 1)) { }
            }
        }
        __syncthreads();
        __threadfence();
    }
}

// ---- K4: logits GEMM (bf16 HMMA, 128x128, 3-stage cp.async, 2 CTA/SM) --------
constexpr int LKCH = 64;                  // k cols per stage
constexpr int LPAD = 72;                  // element stride (144B, conflict-free)
constexpr int LSTG = 128 * LPAD * 2;      // 18432 B per operand-stage
constexpr int LSM_TOT = 6 * LSTG + 1024;  // 3 A + 3 B stages + srow/sbias

__global__ __launch_bounds__(256, 2) void k_logits(const float* __restrict__ bout,
                                                   float* __restrict__ out) {
    extern __shared__ char sm[];
    const unsigned smb = smem_u32(sm);
    const unsigned aBase = smb, bBase = smb + 3 * LSTG;
    float* srow  = (float*)(sm + 6 * LSTG);
    float* sbias = srow + 128;
    const int m0 = blockIdx.x * 128, n0 = blockIdx.y * 128;
    const int tid = threadIdx.x, lane = tid & 31;
    const int w = tid >> 5, wm = w & 1, wn = w >> 1;   // 2 (m) x 4 (n) warps
    const int g = lane >> 2, q = lane & 3;
    const int lr = lane & 7, lh = (lane >> 3) & 1, lq = lane >> 4;
    const int arow = lr + lh * 8, acol = lq * 8;
    const int brow = lr + lq * 8, bcol = lh * 8;

    if (tid < 128) { srow[tid] = 0.f; sbias[tid] = bout[n0 + tid]; }

    float acc[4][4][4];
#pragma unroll
    for (int a = 0; a < 4; a++)
#pragma unroll
        for (int b = 0; b < 4; b++)
#pragma unroll
            for (int c = 0; c < 4; c++) acc[a][b][c] = 0.f;

    auto loadStage = [&](int s) {
        int buf = s % 3;
        const char* asrc = (const char*)(g_hsb + (size_t)m0 * cH + s * LKCH);
        const char* bsrc = (const char*)(g_wob + (size_t)n0 * cH + s * LKCH);
        unsigned ad = aBase + buf * LSTG, bd = bBase + buf * LSTG;
#pragma unroll
        for (int j = 0; j < 4; ++j) {         // 1024 x 16B per operand
            int i = tid + 256 * j;
            int row = i >> 3, cb = (i & 7) * 16;
            cpasync16(ad + row * (LPAD * 2) + cb, asrc + (size_t)row * (cH * 2) + cb);
            cpasync16(bd + row * (LPAD * 2) + cb, bsrc + (size_t)row * (cH * 2) + cb);
        }
        asm volatile("cp.async.commit_group;\n");
    };

    loadStage(0); loadStage(1);
    constexpr int NS = cH / LKCH;   // 16
    for (int s = 0; s < NS; ++s) {
        if (s == NS - 1) asm volatile("cp.async.wait_group 0;\n");
        else             asm volatile("cp.async.wait_group 1;\n");
        __syncthreads();
        if (s + 2 < NS) loadStage(s + 2);
        int buf = s % 3;
        unsigned aS = aBase + buf * LSTG, bS = bBase + buf * LSTG;
#pragma unroll
        for (int kt = 0; kt < 4; ++kt) {
            int kk = kt * 16;
            unsigned a[4][4], bf[2][4];
#pragma unroll
            for (int mt = 0; mt < 4; ++mt)
                ldmat4(a[mt], aS + (((wm * 64 + mt * 16 + arow) * LPAD + kk + acol) << 1));
#pragma unroll
            for (int p = 0; p < 2; ++p)
                ldmat4(bf[p], bS + (((wn * 32 + p * 16 + brow) * LPAD + kk + bcol) << 1));
#pragma unroll
            for (int nt = 0; nt < 4; ++nt) {
                unsigned b0 = bf[nt >> 1][(nt & 1) * 2];
                unsigned b1 = bf[nt >> 1][(nt & 1) * 2 + 1];
#pragma unroll
                for (int mt = 0; mt < 4; ++mt)
                    mma_bf16(acc[mt][nt], a[mt], b0, b1);
            }
        }
    }

    // epilogue: bias + store + exp partial sums
    float es[4][2];
#pragma unroll
    for (int mt = 0; mt < 4; ++mt) { es[mt][0] = 0.f; es[mt][1] = 0.f; }
#pragma unroll
    for (int mt = 0; mt < 4; ++mt)
#pragma unroll
        for (int nt = 0; nt < 4; ++nt) {
            int row = m0 + wm * 64 + mt * 16 + g;
            int lc  = wn * 32 + nt * 8 + 2 * q;
            int col = n0 + lc;
            float v0 = acc[mt][nt][0] + sbias[lc];
            float v1 = acc[mt][nt][1] + sbias[lc + 1];
            float v2 = acc[mt][nt][2] + sbias[lc];
            float v3 = acc[mt][nt][3] + sbias[lc + 1];
            out[(size_t)row * cV + col]           = v0;
            out[(size_t)row * cV + col + 1]       = v1;
            out[(size_t)(row + 8) * cV + col]     = v2;
            out[(size_t)(row + 8) * cV + col + 1] = v3;
            es[mt][0] += __expf(v0) + __expf(v1);
            es[mt][1] += __expf(v2) + __expf(v3);
        }
#pragma unroll
    for (int mt = 0; mt < 4; ++mt)
#pragma unroll
        for (int h = 0; h < 2; ++h) {
            es[mt][h] += __shfl_xor_sync(0xFFFFFFFFu, es[mt][h], 1);
            es[mt][h] += __shfl_xor_sync(0xFFFFFFFFu, es[mt][h], 2);
        }
    if (q == 0) {
#pragma unroll
        for (int mt = 0; mt < 4; ++mt) {
            atomicAdd(&srow[wm * 64 + mt * 16 + g], es[mt][0]);
            atomicAdd(&srow[wm * 64 + mt * 16 + g + 8], es[mt][1]);
        }
    }
    __syncthreads();
    if (tid < 128) atomicAdd(&g_sum[m0 + tid], srow[tid]);
}

// ---- K6: subtract log(sum) in-place (8 CTAs per row) -------------------------
__global__ __launch_bounds__(256) void k_sub(float* __restrict__ out) {
    int row = blockIdx.x;
    float l = logf(g_sum[row]);
    const int seg = blockIdx.y;              // 0..7, 4000 elems each
    float4* p = (float4*)(out + (size_t)row * cV + seg * 4000);
    for (int i = threadIdx.x; i < 1000; i += 256) {
        float4 v = p[i];
        v.x -= l; v.y -= l; v.z -= l; v.w -= l;
        p[i] = v;
    }
}

extern "C" void kernel_launch(void* const* d_in, const int* in_sizes, int n_in,
                              void* d_out, int out_size) {
    const float* enc_hidden = (const float*)d_in[1];
    const int*   target     = (const int*)d_in[2];
    const float* emb        = (const float*)d_in[3];
    const float* w_ih       = (const float*)d_in[4];
    const float* w_hh       = (const float*)d_in[5];
    const float* b_ih       = (const float*)d_in[6];
    const float* b_hh       = (const float*)d_in[7];
    const float* w_out      = (const float*)d_in[8];
    const float* b_out      = (const float*)d_in[9];
    float* out = (float*)d_out;

    constexpr int RSMEM = (24 * WSTR + 3 * 32 * HSTR) * 4 + (3 * 32 * 9 + 32 * 8 + 24) * 4;
    cudaFuncSetAttribute(k_rnn, cudaFuncAttributeMaxDynamicSharedMemorySize, RSMEM);
    cudaFuncSetAttribute(k_logits, cudaFuncAttributeMaxDynamicSharedMemorySize, LSM_TOT);
    cudaFuncSetAttribute(k_gi, cudaFuncAttributeMaxDynamicSharedMemorySize, GSM_TOT);

    k_pre<<<cV + cG + cM + cB * cH / 256, 256>>>(target, emb, w_out, w_ih, enc_hidden);
    k_gi<<<dim3(cM / 128, cG / 128), 256, GSM_TOT>>>(b_ih);
    k_rnn<<<NCTA, RTHREADS, RSMEM>>>(enc_hidden, w_hh, b_hh, out + cBTV);
    k_logits<<<dim3(cM / 128, cV / 128), 256, LSM_TOT>>>(b_out, out);
    k_sub<<<dim3(cM, 8), 256>>>(out);
}

// round 12
// speedup vs baseline: 2.2615x; 1.0512x over previous
#include <cuda_runtime.h>
#include <cuda_bf16.h>
#include <cstdint>

constexpr int cV = 32000, cH = 1024, cB = 32, cT = 64;
constexpr int cM = cB * cT;           // 2048
constexpr int cG = 3 * cH;            // 3072
constexpr long long cBTV = (long long)cB * cT * cV;

constexpr int NCTA = 128;             // recurrence CTAs
constexpr int UPC  = 8;               // hidden units per CTA
constexpr int RTHREADS = 192;         // 6 warps: (gate, m-half)

__device__ __align__(16) unsigned      g_X[cM * cH];             // tf32 relu(embed)
__device__ __align__(16) unsigned      g_wihtf[(size_t)cG * cH]; // tf32 w_ih
__device__ __align__(16) float         g_gi[(size_t)cM * cG];
__device__ __align__(16) unsigned      g_htf[2][cB * cH];        // tf32 h ping-pong
__device__ __align__(16) __nv_bfloat16 g_hsb[cM * cH];           // [b*T+t][H]
__device__ __align__(16) __nv_bfloat16 g_wob[(size_t)cV * cH];
__device__ float g_sum[cM];
__device__ unsigned g_flags[NCTA * 32];   // 128B-strided barrier slots

__device__ __forceinline__ unsigned f2tf(float f) {
    unsigned u; asm("cvt.rna.tf32.f32 %0, %1;" : "=r"(u) : "f"(f)); return u;
}
__device__ __forceinline__ unsigned smem_u32(const void* p) {
    unsigned a;
    asm("{ .reg .u64 t; cvta.to.shared.u64 t, %1; cvt.u32.u64 %0, t; }" : "=r"(a) : "l"(p));
    return a;
}
__device__ __forceinline__ void mma_tf32(float* c, const unsigned* a, unsigned b0, unsigned b1) {
    asm volatile("mma.sync.aligned.m16n8k8.row.col.f32.tf32.tf32.f32 "
        "{%0,%1,%2,%3}, {%4,%5,%6,%7}, {%8,%9}, {%0,%1,%2,%3};\n"
        : "+f"(c[0]), "+f"(c[1]), "+f"(c[2]), "+f"(c[3])
        : "r"(a[0]), "r"(a[1]), "r"(a[2]), "r"(a[3]), "r"(b0), "r"(b1));
}
__device__ __forceinline__ void mma_bf16(float* c, const unsigned* a, unsigned b0, unsigned b1) {
    asm volatile("mma.sync.aligned.m16n8k16.row.col.f32.bf16.bf16.f32 "
        "{%0,%1,%2,%3}, {%4,%5,%6,%7}, {%8,%9}, {%0,%1,%2,%3};\n"
        : "+f"(c[0]), "+f"(c[1]), "+f"(c[2]), "+f"(c[3])
        : "r"(a[0]), "r"(a[1]), "r"(a[2]), "r"(a[3]), "r"(b0), "r"(b1));
}
__device__ __forceinline__ void ldmat4(unsigned* r, unsigned addr) {
    asm volatile("ldmatrix.sync.aligned.m8n8.x4.shared.b16 {%0,%1,%2,%3}, [%4];"
        : "=r"(r[0]), "=r"(r[1]), "=r"(r[2]), "=r"(r[3]) : "r"(addr));
}
__device__ __forceinline__ void cpasync16(unsigned dst, const void* src) {
    asm volatile("cp.async.cg.shared.global [%0], [%1], 16;\n" :: "r"(dst), "l"(src));
}

// ---- K0: fused preamble ------------------------------------------------------
__global__ void k_pre(const int* __restrict__ target, const float* __restrict__ emb,
                      const float* __restrict__ w_out, const float* __restrict__ w_ih,
                      const float* __restrict__ h0) {
    int bx = blockIdx.x;
    if (bx < cV) {
        size_t i = (size_t)bx * 1024 + threadIdx.x * 4;
        float4 v = *(const float4*)(w_out + i);
        *(__nv_bfloat162*)(g_wob + i)     = __floats2bfloat162_rn(v.x, v.y);
        *(__nv_bfloat162*)(g_wob + i + 2) = __floats2bfloat162_rn(v.z, v.w);
    } else if (bx < cV + cG) {
        size_t i = (size_t)(bx - cV) * 1024 + threadIdx.x * 4;
        float4 v = *(const float4*)(w_ih + i);
        uint4 o; o.x = f2tf(v.x); o.y = f2tf(v.y); o.z = f2tf(v.z); o.w = f2tf(v.w);
        *(uint4*)(g_wihtf + i) = o;
    } else if (bx < cV + cG + cM) {
        int m = bx - cV - cG, t = m >> 5, b = m & 31;
        int tok = (t == 0) ? 1 : target[b * cT + (t - 1)];
        float4 v = ((const float4*)(emb + (size_t)tok * cH))[threadIdx.x];
        uint4 o;
        o.x = f2tf(fmaxf(v.x, 0.f)); o.y = f2tf(fmaxf(v.y, 0.f));
        o.z = f2tf(fmaxf(v.z, 0.f)); o.w = f2tf(fmaxf(v.w, 0.f));
        ((uint4*)(g_X + (size_t)m * cH))[threadIdx.x] = o;
    } else {
        int i = (bx - cV - cG - cM) * 256 + threadIdx.x;
        g_htf[0][i] = f2tf(h0[i]);
        if (i < cM) g_sum[i] = 0.f;
        if (i < NCTA * 32) g_flags[i] = 0;
    }
}

// ---- K2: gi = X @ w_ih^T + b_ih (tf32, 128x128 tile, 3-stage, 2 CTA/SM) ------
constexpr int GKCH = 32;
constexpr int GPAD = 36;
constexpr int GSTG = 128 * GPAD * 4;       // 18432 B
constexpr int GSM_TOT = 6 * GSTG + 16;

__global__ __launch_bounds__(256, 2) void k_gi(const float* __restrict__ bih) {
    extern __shared__ char smg[];
    const unsigned smb = smem_u32(smg);
    const unsigned aBase = smb, bBase = smb + 3 * GSTG;
    const int m0 = blockIdx.x * 128, n0 = blockIdx.y * 128;
    const int tid = threadIdx.x, lane = tid & 31;
    const int w = tid >> 5, wm = w & 1, wn = w >> 1;
    const int g = lane >> 2, q = lane & 3;

    float acc[4][4][4];
#pragma unroll
    for (int a = 0; a < 4; a++)
#pragma unroll
        for (int b = 0; b < 4; b++)
#pragma unroll
            for (int c = 0; c < 4; c++) acc[a][b][c] = 0.f;

    auto loadStage = [&](int s) {
        int buf = s % 3;
        const char* asrc = (const char*)(g_X + (size_t)m0 * cH + s * GKCH);
        const char* bsrc = (const char*)(g_wihtf + (size_t)n0 * cH + s * GKCH);
        unsigned ad = aBase + buf * GSTG, bd = bBase + buf * GSTG;
#pragma unroll
        for (int j = 0; j < 4; ++j) {
            int i = tid + 256 * j;
            int row = i >> 3, cb = (i & 7) * 16;
            cpasync16(ad + row * (GPAD * 4) + cb, asrc + (size_t)row * (cH * 4) + cb);
            cpasync16(bd + row * (GPAD * 4) + cb, bsrc + (size_t)row * (cH * 4) + cb);
        }
        asm volatile("cp.async.commit_group;\n");
    };

    loadStage(0); loadStage(1);
    constexpr int NS = cH / GKCH;   // 32
    for (int s = 0; s < NS; ++s) {
        if (s == NS - 1) asm volatile("cp.async.wait_group 0;\n");
        else             asm volatile("cp.async.wait_group 1;\n");
        __syncthreads();
        if (s + 2 < NS) loadStage(s + 2);
        int buf = s % 3;
        const unsigned* aS = (const unsigned*)(smg + buf * GSTG);
        const unsigned* bS = (const unsigned*)(smg + 3 * GSTG + buf * GSTG);
#pragma unroll
        for (int kt = 0; kt < 4; ++kt) {
            int kk = kt * 8;
            unsigned a[4][4];
#pragma unroll
            for (int mt = 0; mt < 4; ++mt) {
                int r = wm * 64 + mt * 16 + g;
                a[mt][0] = aS[r * GPAD + kk + q];
                a[mt][1] = aS[(r + 8) * GPAD + kk + q];
                a[mt][2] = aS[r * GPAD + kk + q + 4];
                a[mt][3] = aS[(r + 8) * GPAD + kk + q + 4];
            }
#pragma unroll
            for (int nt = 0; nt < 4; ++nt) {
                int c = wn * 32 + nt * 8 + g;
                unsigned b0 = bS[c * GPAD + kk + q];
                unsigned b1 = bS[c * GPAD + kk + q + 4];
#pragma unroll
                for (int mt = 0; mt < 4; ++mt)
                    mma_tf32(acc[mt][nt], a[mt], b0, b1);
            }
        }
    }
#pragma unroll
    for (int mt = 0; mt < 4; ++mt)
#pragma unroll
        for (int nt = 0; nt < 4; ++nt) {
            int row = m0 + wm * 64 + mt * 16 + g;
            int col = n0 + wn * 32 + nt * 8 + 2 * q;
            float b0 = bih[col], b1 = bih[col + 1];
            g_gi[(size_t)row * cG + col]           = acc[mt][nt][0] + b0;
            g_gi[(size_t)row * cG + col + 1]       = acc[mt][nt][1] + b1;
            g_gi[(size_t)(row + 8) * cG + col]     = acc[mt][nt][2] + b0;
            g_gi[(size_t)(row + 8) * cG + col + 1] = acc[mt][nt][3] + b1;
        }
}

// ---- K3: persistent GRU recurrence (tf32, 192 threads, warp=(gate,m-half)) ---
constexpr int WSTR = 1028;
constexpr int HSTR = 260;     // 256 + 4 pad words

__global__ __launch_bounds__(RTHREADS) void k_rnn(const float* __restrict__ h0,
                                                  const float* __restrict__ Whh,
                                                  const float* __restrict__ bhh,
                                                  float* __restrict__ outh) {
    extern __shared__ unsigned su[];
    unsigned* w_s  = su;                        // 24 * WSTR
    unsigned* h_s  = w_s + 24 * WSTR;           // 3 * 32 * HSTR
    float*    sGH  = (float*)(h_s + 3 * 32 * HSTR);
    float*    h_own = sGH + 3 * 32 * 9;
    float*    bhh_s = h_own + 32 * 8;

    const int tid = threadIdx.x, lane = tid & 31, w = tid >> 5;
    const int gate = w >> 1, mh = w & 1;        // warp = (gate, m-half)
    const int g = lane >> 2, q = lane & 3;
    const int u0 = blockIdx.x * UPC;

    for (int i = tid; i < 24 * 256; i += RTHREADS) {
        int r = i >> 8, c4 = (i & 255) * 4;
        int gt = r >> 3, rr = r & 7;
        float4 v = *(const float4*)(Whh + ((size_t)gt * cH + u0 + rr) * cH + c4);
        unsigned* p = &w_s[r * WSTR + c4];
        p[0] = f2tf(v.x); p[1] = f2tf(v.y); p[2] = f2tf(v.z); p[3] = f2tf(v.w);
    }
    if (tid < 24) bhh_s[tid] = bhh[(tid >> 3) * cH + u0 + (tid & 7)];
    for (int i = tid; i < 32 * 8; i += RTHREADS)
        h_own[i] = h0[(i >> 3) * cH + u0 + (i & 7)];
    __syncthreads();

    for (int t = 0; t < cT; ++t) {
        float gr[2], gz[2], gn[2];
#pragma unroll
        for (int j = 0; j < 2; ++j) {
            int idx = tid + RTHREADS * j;
            if (idx < 256) {
                int b = idx >> 3, u = idx & 7;
                const float* gi = g_gi + ((size_t)t * cB + b) * cG + u0 + u;
                gr[j] = gi[0]; gz[j] = gi[cH]; gn[j] = gi[2 * cH];
            }
        }
        const unsigned* hsrc = g_htf[t & 1];
        auto ldchunk = [&](int ki) {
            int buf = ki % 3, kc = ki * 256;
            for (int i = tid; i < 2048; i += RTHREADS) {   // 32 rows x 64 uint4
                int r = i >> 6, c4 = (i & 63) * 4;
                cpasync16(smem_u32(&h_s[buf * 32 * HSTR + r * HSTR + c4]),
                          hsrc + r * cH + kc + c4);
            }
            asm volatile("cp.async.commit_group;\n");
        };
        ldchunk(0); ldchunk(1);
        float acc[4] = {0.f, 0.f, 0.f, 0.f};
        for (int ki = 0; ki < 4; ++ki) {
            if (ki == 3) asm volatile("cp.async.wait_group 0;\n");
            else         asm volatile("cp.async.wait_group 1;\n");
            __syncthreads();
            if (ki + 2 < 4) ldchunk(ki + 2);
            const unsigned* hb = &h_s[(ki % 3) * 32 * HSTR];
            const unsigned* wb = &w_s[gate * 8 * WSTR + ki * 256];
#pragma unroll
            for (int kk = 0; kk < 32; ++kk) {
                int kcol = kk * 8;
                unsigned b0 = wb[g * WSTR + kcol + q];
                unsigned b1 = wb[g * WSTR + kcol + q + 4];
                unsigned a[4];
                a[0] = hb[(mh * 16 + g) * HSTR + kcol + q];
                a[1] = hb[(mh * 16 + g + 8) * HSTR + kcol + q];
                a[2] = hb[(mh * 16 + g) * HSTR + kcol + q + 4];
                a[3] = hb[(mh * 16 + g + 8) * HSTR + kcol + q + 4];
                mma_tf32(acc, a, b0, b1);
            }
        }
        __syncthreads();
        float* sg = sGH + gate * (32 * 9);
        sg[(mh * 16 + g) * 9 + 2 * q]         = acc[0];
        sg[(mh * 16 + g) * 9 + 2 * q + 1]     = acc[1];
        sg[(mh * 16 + g + 8) * 9 + 2 * q]     = acc[2];
        sg[(mh * 16 + g + 8) * 9 + 2 * q + 1] = acc[3];
        __syncthreads();
#pragma unroll
        for (int j = 0; j < 2; ++j) {
            int idx = tid + RTHREADS * j;
            if (idx < 256) {
                int b = idx >> 3, u = idx & 7;
                float pr = gr[j] + sGH[0 * 288 + b * 9 + u] + bhh_s[u];
                float pz = gz[j] + sGH[1 * 288 + b * 9 + u] + bhh_s[8 + u];
                float hn = sGH[2 * 288 + b * 9 + u] + bhh_s[16 + u];
                float r = 1.f / (1.f + expf(-pr));
                float z = 1.f / (1.f + expf(-pz));
                float n = tanhf(gn[j] + r * hn);
                float hv = (1.f - z) * n + z * h_own[idx];
                h_own[idx] = hv;
                g_htf[(t + 1) & 1][b * cH + u0 + u] = f2tf(hv);
                g_hsb[((size_t)b * cT + t) * cH + u0 + u] = __float2bfloat16(hv);
                if (t == cT - 1) outh[b * cH + u0 + u] = hv;
            }
        }
        __threadfence();
        __syncthreads();
        if (tid == 0) ((volatile unsigned*)g_flags)[blockIdx.x * 32] = t + 1;
        if (tid < NCTA)
            while (((volatile unsigned*)g_flags)[tid * 32] < (unsigned)(t + 1)) { }
        __syncthreads();
        __threadfence();
    }
}

// ---- K4: logits GEMM (bf16 HMMA, 128x128, 3-stage cp.async, 2 CTA/SM) --------
constexpr int LKCH = 64;
constexpr int LPAD = 72;
constexpr int LSTG = 128 * LPAD * 2;      // 18432 B
constexpr int LSM_TOT = 6 * LSTG + 1024;

__global__ __launch_bounds__(256, 2) void k_logits(const float* __restrict__ bout,
                                                   float* __restrict__ out) {
    extern __shared__ char sm[];
    const unsigned smb = smem_u32(sm);
    const unsigned aBase = smb, bBase = smb + 3 * LSTG;
    float* srow  = (float*)(sm + 6 * LSTG);
    float* sbias = srow + 128;
    const int m0 = blockIdx.x * 128, n0 = blockIdx.y * 128;
    const int tid = threadIdx.x, lane = tid & 31;
    const int w = tid >> 5, wm = w & 1, wn = w >> 1;
    const int g = lane >> 2, q = lane & 3;
    const int lr = lane & 7, lh = (lane >> 3) & 1, lq = lane >> 4;
    const int arow = lr + lh * 8, acol = lq * 8;
    const int brow = lr + lq * 8, bcol = lh * 8;

    if (tid < 128) { srow[tid] = 0.f; sbias[tid] = bout[n0 + tid]; }

    float acc[4][4][4];
#pragma unroll
    for (int a = 0; a < 4; a++)
#pragma unroll
        for (int b = 0; b < 4; b++)
#pragma unroll
            for (int c = 0; c < 4; c++) acc[a][b][c] = 0.f;

    auto loadStage = [&](int s) {
        int buf = s % 3;
        const char* asrc = (const char*)(g_hsb + (size_t)m0 * cH + s * LKCH);
        const char* bsrc = (const char*)(g_wob + (size_t)n0 * cH + s * LKCH);
        unsigned ad = aBase + buf * LSTG, bd = bBase + buf * LSTG;
#pragma unroll
        for (int j = 0; j < 4; ++j) {
            int i = tid + 256 * j;
            int row = i >> 3, cb = (i & 7) * 16;
            cpasync16(ad + row * (LPAD * 2) + cb, asrc + (size_t)row * (cH * 2) + cb);
            cpasync16(bd + row * (LPAD * 2) + cb, bsrc + (size_t)row * (cH * 2) + cb);
        }
        asm volatile("cp.async.commit_group;\n");
    };

    loadStage(0); loadStage(1);
    constexpr int NS = cH / LKCH;   // 16
    for (int s = 0; s < NS; ++s) {
        if (s == NS - 1) asm volatile("cp.async.wait_group 0;\n");
        else             asm volatile("cp.async.wait_group 1;\n");
        __syncthreads();
        if (s + 2 < NS) loadStage(s + 2);
        int buf = s % 3;
        unsigned aS = aBase + buf * LSTG, bS = bBase + buf * LSTG;
#pragma unroll
        for (int kt = 0; kt < 4; ++kt) {
            int kk = kt * 16;
            unsigned a[4][4], bf[2][4];
#pragma unroll
            for (int mt = 0; mt < 4; ++mt)
                ldmat4(a[mt], aS + (((wm * 64 + mt * 16 + arow) * LPAD + kk + acol) << 1));
#pragma unroll
            for (int p = 0; p < 2; ++p)
                ldmat4(bf[p], bS + (((wn * 32 + p * 16 + brow) * LPAD + kk + bcol) << 1));
#pragma unroll
            for (int nt = 0; nt < 4; ++nt) {
                unsigned b0 = bf[nt >> 1][(nt & 1) * 2];
                unsigned b1 = bf[nt >> 1][(nt & 1) * 2 + 1];
#pragma unroll
                for (int mt = 0; mt < 4; ++mt)
                    mma_bf16(acc[mt][nt], a[mt], b0, b1);
            }
        }
    }

    float es[4][2];
#pragma unroll
    for (int mt = 0; mt < 4; ++mt) { es[mt][0] = 0.f; es[mt][1] = 0.f; }
#pragma unroll
    for (int mt = 0; mt < 4; ++mt)
#pragma unroll
        for (int nt = 0; nt < 4; ++nt) {
            int row = m0 + wm * 64 + mt * 16 + g;
            int lc  = wn * 32 + nt * 8 + 2 * q;
            int col = n0 + lc;
            float v0 = acc[mt][nt][0] + sbias[lc];
            float v1 = acc[mt][nt][1] + sbias[lc + 1];
            float v2 = acc[mt][nt][2] + sbias[lc];
            float v3 = acc[mt][nt][3] + sbias[lc + 1];
            out[(size_t)row * cV + col]           = v0;
            out[(size_t)row * cV + col + 1]       = v1;
            out[(size_t)(row + 8) * cV + col]     = v2;
            out[(size_t)(row + 8) * cV + col + 1] = v3;
            es[mt][0] += __expf(v0) + __expf(v1);
            es[mt][1] += __expf(v2) + __expf(v3);
        }
#pragma unroll
    for (int mt = 0; mt < 4; ++mt)
#pragma unroll
        for (int h = 0; h < 2; ++h) {
            es[mt][h] += __shfl_xor_sync(0xFFFFFFFFu, es[mt][h], 1);
            es[mt][h] += __shfl_xor_sync(0xFFFFFFFFu, es[mt][h], 2);
        }
    if (q == 0) {
#pragma unroll
        for (int mt = 0; mt < 4; ++mt) {
            atomicAdd(&srow[wm * 64 + mt * 16 + g], es[mt][0]);
            atomicAdd(&srow[wm * 64 + mt * 16 + g + 8], es[mt][1]);
        }
    }
    __syncthreads();
    if (tid < 128) atomicAdd(&g_sum[m0 + tid], srow[tid]);
}

// ---- K6: subtract log(sum) in-place (8 CTAs per row) -------------------------
__global__ __launch_bounds__(256) void k_sub(float* __restrict__ out) {
    int row = blockIdx.x;
    float l = logf(g_sum[row]);
    const int seg = blockIdx.y;              // 0..7, 4000 elems each
    float4* p = (float4*)(out + (size_t)row * cV + seg * 4000);
    for (int i = threadIdx.x; i < 1000; i += 256) {
        float4 v = p[i];
        v.x -= l; v.y -= l; v.z -= l; v.w -= l;
        p[i] = v;
    }
}

extern "C" void kernel_launch(void* const* d_in, const int* in_sizes, int n_in,
                              void* d_out, int out_size) {
    const float* enc_hidden = (const float*)d_in[1];
    const int*   target     = (const int*)d_in[2];
    const float* emb        = (const float*)d_in[3];
    const float* w_ih       = (const float*)d_in[4];
    const float* w_hh       = (const float*)d_in[5];
    const float* b_ih       = (const float*)d_in[6];
    const float* b_hh       = (const float*)d_in[7];
    const float* w_out      = (const float*)d_in[8];
    const float* b_out      = (const float*)d_in[9];
    float* out = (float*)d_out;

    constexpr int RSMEM = (24 * WSTR + 3 * 32 * HSTR) * 4 + (3 * 32 * 9 + 32 * 8 + 24) * 4;
    cudaFuncSetAttribute(k_rnn, cudaFuncAttributeMaxDynamicSharedMemorySize, RSMEM);
    cudaFuncSetAttribute(k_logits, cudaFuncAttributeMaxDynamicSharedMemorySize, LSM_TOT);
    cudaFuncSetAttribute(k_gi, cudaFuncAttributeMaxDynamicSharedMemorySize, GSM_TOT);

    k_pre<<<cV + cG + cM + cB * cH / 256, 256>>>(target, emb, w_out, w_ih, enc_hidden);
    k_gi<<<dim3(cM / 128, cG / 128), 256, GSM_TOT>>>(b_ih);
    k_rnn<<<NCTA, RTHREADS, RSMEM>>>(enc_hidden, w_hh, b_hh, out + cBTV);
    k_logits<<<dim3(cM / 128, cV / 128), 256, LSM_TOT>>>(b_out, out);
    k_sub<<<dim3(cM, 8), 256>>>(out);
}